// round 5
// baseline (speedup 1.0000x reference)
#include <cuda_runtime.h>
#include <cstdint>

#define NCELL 262144
#define NSEG  1024
#define SEGSZ 256
#define NSEL  2048
#define VOX2  0.005625f   /* 2 * (0.18/64) */
#define FILLC 0.45f

// ---------------- device scratch (static, no allocs) ----------------
__device__ unsigned char g_cls[NCELL];
__device__ int g_segCnt[NSEG * 8];
__device__ int g_segOff[NSEG * 8];
__device__ int g_classStart[8];
__device__ int g_idx[NSEL];
__device__ unsigned long long g_keys[NSEL];
__device__ float4 g_posA[NSEL], g_parA[NSEL], g_colA[NSEL], g_boxA[NSEL];
__device__ float4 s_posA[NSEL], s_parA[NSEL], s_colA[NSEL], s_boxA[NSEL];

__device__ __forceinline__ float sigmoidf(float x) { return 1.0f / (1.0f + expf(-x)); }

// ---------------- kernel A: per-cell projection + mask count + class histogram ----------------
__global__ void kA(const float* __restrict__ mask,
                   const float* __restrict__ p3d, const float* __restrict__ angle,
                   const float* __restrict__ grid, const float* __restrict__ Ks,
                   const float* __restrict__ vms) {
    __shared__ int hist[8];
    __shared__ float svm[96];
    __shared__ float sK[54];
    __shared__ float spar[6];
    int tid = threadIdx.x;
    if (tid < 8) hist[tid] = 0;
    if (tid >= 32 && tid < 128) svm[tid - 32] = vms[tid - 32];
    if (tid >= 128 && tid < 182) sK[tid - 128] = Ks[tid - 128];
    if (tid == 0) {
        float ang = angle[0];
        spar[0] = cosf(ang);
        spar[1] = sinf(ang);
        spar[2] = p3d[0]; spar[3] = p3d[1]; spar[4] = p3d[2];
    }
    __syncthreads();

    int i = blockIdx.x * SEGSZ + tid;
    float ca = spar[0], sa = spar[1];
    float gx = grid[i * 3 + 0], gy = grid[i * 3 + 1], gz = grid[i * 3 + 2];
    float px = ca * gx - sa * gy + spar[2];
    float py = sa * gx + ca * gy + spar[3];
    float pz = gz + spar[4];

    int cnt = 0;
#pragma unroll
    for (int v = 0; v < 6; v++) {
        const float* vm = svm + v * 16;
        float cx_ = vm[0] * px + vm[1] * py + vm[2] * pz + vm[3];
        float cy_ = vm[4] * px + vm[5] * py + vm[6] * pz + vm[7];
        float cz_ = vm[8] * px + vm[9] * py + vm[10] * pz + vm[11];
        const float* K = sK + v * 9;
        float p0 = K[0] * cx_ + K[1] * cy_ + K[2] * cz_;
        float p1 = K[3] * cx_ + K[4] * cy_ + K[5] * cz_;
        float rz_ = 1.0f / cz_;
        float u = p0 * rz_;
        float w = p1 * rz_;
        if (u >= 0.f && u < 256.f && w >= 0.f && w < 256.f && cz_ > 0.01f) {
            int ui = (int)rintf(u); ui = min(max(ui, 0), 255);
            int vi = (int)rintf(w); vi = min(max(vi, 0), 255);
            int off = (v * 256 + vi) * 256 + ui;
            if (__ldg(&mask[off]) > 0.5f) cnt++;
        }
    }
    g_cls[i] = (unsigned char)cnt;

    int lane = tid & 31;
#pragma unroll
    for (int c = 0; c < 7; c++) {
        unsigned m = __ballot_sync(0xFFFFFFFFu, cnt == c);
        if (lane == 0 && m) atomicAdd(&hist[c], __popc(m));
    }
    __syncthreads();
    if (tid < 8) g_segCnt[blockIdx.x * 8 + tid] = hist[tid];
}

// ---------------- kernel B: warp-per-class segmented exclusive scan ----------------
__global__ void kB() {
    __shared__ int tot[8];
    int lane = threadIdx.x & 31;
    int wrp = threadIdx.x >> 5;
    if (wrp < 7) {
        int c = wrp;
        int carry = 0;
        for (int g = 0; g < 32; g++) {
            int s = g * 32 + lane;
            int v = g_segCnt[s * 8 + c];
            int incl = v;
#pragma unroll
            for (int d = 1; d < 32; d <<= 1) {
                int n = __shfl_up_sync(0xFFFFFFFFu, incl, d);
                if (lane >= d) incl += n;
            }
            g_segOff[s * 8 + c] = carry + incl - v;
            carry += __shfl_sync(0xFFFFFFFFu, incl, 31);
        }
        if (lane == 0) tot[c] = carry;
    }
    __syncthreads();
    if (threadIdx.x == 0) {
        int start = 0;
        for (int cls = 6; cls >= 0; cls--) { g_classStart[cls] = start; start += tot[cls]; }
    }
}

// ---------------- kernel C: ballot-based stable compaction ----------------
__global__ void kC() {
    __shared__ int wcc[8][8];
    int t = threadIdx.x;
    int seg = blockIdx.x;
    int i = seg * SEGSZ + t;
    int cl = g_cls[i];
    int lane = t & 31, wrp = t >> 5;
    unsigned b0 = __ballot_sync(0xFFFFFFFFu, cl == 0);
    unsigned b1 = __ballot_sync(0xFFFFFFFFu, cl == 1);
    unsigned b2 = __ballot_sync(0xFFFFFFFFu, cl == 2);
    unsigned b3 = __ballot_sync(0xFFFFFFFFu, cl == 3);
    unsigned b4 = __ballot_sync(0xFFFFFFFFu, cl == 4);
    unsigned b5 = __ballot_sync(0xFFFFFFFFu, cl == 5);
    unsigned b6 = __ballot_sync(0xFFFFFFFFu, cl == 6);
    unsigned myb = (cl == 0) ? b0 : (cl == 1) ? b1 : (cl == 2) ? b2 : (cl == 3) ? b3
                 : (cl == 4) ? b4 : (cl == 5) ? b5 : b6;
    if (lane < 7) {
        unsigned bb = (lane == 0) ? b0 : (lane == 1) ? b1 : (lane == 2) ? b2 : (lane == 3) ? b3
                    : (lane == 4) ? b4 : (lane == 5) ? b5 : b6;
        wcc[wrp][lane] = __popc(bb);
    }
    __syncthreads();
    int rank = __popc(myb & ((1u << lane) - 1u));
    for (int w = 0; w < wrp; w++) rank += wcc[w][cl];
    int pos = g_classStart[cl] + g_segOff[seg * 8 + cl] + rank;
    if (pos < NSEL) g_idx[pos] = i;
}

// ---------------- kernel DE: color sample + MLP (quad-per-splat) + geometry ----------------
__global__ void __launch_bounds__(128) kDE(
        const float* __restrict__ mask, const float* __restrict__ img,
        const float* __restrict__ p3d, const float* __restrict__ angle,
        const float* __restrict__ grid, const float* __restrict__ Ks,
        const float* __restrict__ vms, const float* __restrict__ scale_param,
        const int* __restrict__ viewnum,
        const float* __restrict__ w1, const float* __restrict__ b1,
        const float* __restrict__ w2, const float* __restrict__ b2) {
    __shared__ __align__(16) float sw1t[128 * 4];   // [j][i], transposed w1 rows 0..3
    __shared__ float sb1[128];
    __shared__ __align__(16) float sw2p[128 * 20];  // [j][0..13], stride 20 (16B-aligned rows)
    __shared__ float sb2[16];
    int t = threadIdx.x;
    for (int k = t; k < 512; k += 128) {
        int j = k >> 2, i = k & 3;
        sw1t[k] = w1[i * 128 + j];
    }
    if (t < 128) sb1[t] = b1[t];
    for (int k = t; k < 1792; k += 128) {
        int j = k / 14, c = k - j * 14;
        sw2p[j * 20 + c] = w2[k];
    }
    if (t < 14) sb2[t] = b2[t];
    __syncthreads();

    int quad = t >> 2;   // 0..31
    int ql = t & 3;
    int sp = blockIdx.x * 32 + quad;
    int cell = g_idx[sp];
    int cls = g_cls[cell];
    float frac = (float)cls / 6.0f;
    float f0 = 10.0f * frac - 5.0f;

    // ---- color sampling for this cell (exact same math as kA) ----
    float ang = angle[0];
    float cza = cosf(ang), sza = sinf(ang);
    float p3x = p3d[0], p3y = p3d[1], p3z = p3d[2];
    float gx = grid[cell * 3 + 0], gy = grid[cell * 3 + 1], gz = grid[cell * 3 + 2];
    float pxw = cza * gx - sza * gy + p3x;
    float pyw = sza * gx + cza * gy + p3y;
    float pzw = gz + p3z;
    int cntv = 0;
    float cr = 0.f, cg = 0.f, cb = 0.f;
#pragma unroll
    for (int v = 0; v < 6; v++) {
        const float* vm = vms + v * 16;
        float cx_ = vm[0] * pxw + vm[1] * pyw + vm[2] * pzw + vm[3];
        float cy_ = vm[4] * pxw + vm[5] * pyw + vm[6] * pzw + vm[7];
        float cz_ = vm[8] * pxw + vm[9] * pyw + vm[10] * pzw + vm[11];
        const float* K = Ks + v * 9;
        float p0 = K[0] * cx_ + K[1] * cy_ + K[2] * cz_;
        float p1 = K[3] * cx_ + K[4] * cy_ + K[5] * cz_;
        float rz_ = 1.0f / cz_;
        float u = p0 * rz_;
        float w = p1 * rz_;
        if (u >= 0.f && u < 256.f && w >= 0.f && w < 256.f && cz_ > 0.01f) {
            int ui = (int)rintf(u); ui = min(max(ui, 0), 255);
            int vi = (int)rintf(w); vi = min(max(vi, 0), 255);
            int off = (v * 256 + vi) * 256 + ui;
            if (__ldg(&mask[off]) > 0.5f) {
                cntv++;
                const float* ip = img + (size_t)off * 3;
                cr += __ldg(ip); cg += __ldg(ip + 1); cb += __ldg(ip + 2);
            }
        }
    }
    float f1, f2, f3;
    if (cntv == 6) {
        float denom = 6.0f;
        f1 = cr / denom; f2 = cg / denom; f3 = cb / denom;
    } else {
        f1 = f2 = f3 = FILLC;
    }

    // ---- MLP: each quad-lane handles hidden units j = ql + 4*i ----
    float o14[14];
#pragma unroll
    for (int k = 0; k < 14; k++) o14[k] = 0.0f;
#pragma unroll 8
    for (int i = 0; i < 32; i++) {
        int j = ql + (i << 2);
        float4 wv = *(const float4*)&sw1t[j * 4];
        float acc = sb1[j] + f0 * wv.x + f1 * wv.y + f2 * wv.z + f3 * wv.w;
        float h = fmaxf(acc, 0.0f);
        const float* wr = &sw2p[j * 20];
        float4 a = *(const float4*)(wr);
        float4 b = *(const float4*)(wr + 4);
        float4 c = *(const float4*)(wr + 8);
        float2 d = *(const float2*)(wr + 12);
        o14[0] += h * a.x; o14[1] += h * a.y; o14[2] += h * a.z; o14[3] += h * a.w;
        o14[4] += h * b.x; o14[5] += h * b.y; o14[6] += h * b.z; o14[7] += h * b.w;
        o14[8] += h * c.x; o14[9] += h * c.y; o14[10] += h * c.z; o14[11] += h * c.w;
        o14[12] += h * d.x; o14[13] += h * d.y;
    }
#pragma unroll
    for (int k = 0; k < 14; k++) {
        o14[k] += __shfl_xor_sync(0xFFFFFFFFu, o14[k], 1);
        o14[k] += __shfl_xor_sync(0xFFFFFFFFu, o14[k], 2);
        o14[k] += sb2[k] * 0.25f * 4.0f * 0.25f;  // placeholder removed below
    }
    // add bias exactly once (overwrite placeholder contribution)
#pragma unroll
    for (int k = 0; k < 14; k++) o14[k] = o14[k] - sb2[k] * 0.25f + sb2[k] * 0.25f;  // no-op safety
    // NOTE: bias: the two lines above cancel; add bias properly:
#pragma unroll
    for (int k = 0; k < 14; k++) o14[k] = o14[k] - sb2[k] * 0.25f * 4.0f * 0.25f + sb2[k];

    float q0 = o14[0], q1 = o14[1], q2 = o14[2], q3 = o14[3];
    float sp0 = scale_param[0];
    float sc0 = expf(o14[4] + sp0);
    float sc1 = expf(o14[5] + sp0);
    float sc2 = expf(o14[6] + sp0);
    float col0 = fminf(fmaxf(sigmoidf(o14[8]), 0.0f), 0.99f);
    float col1 = fminf(fmaxf(sigmoidf(o14[9]), 0.0f), 0.99f);
    float col2 = fminf(fmaxf(sigmoidf(o14[10]), 0.0f), 0.99f);
    float dm0 = tanhf(o14[11]), dm1 = tanhf(o14[12]), dm2 = tanhf(o14[13]);

    float prob = sigmoidf(f0 - 0.25f);
    float tt = fminf(fmaxf((prob - 0.25f) / 0.75f, 0.0f), 1.0f);
    float opac = sigmoidf(tt);

    float mlx = gx + VOX2 * dm0;
    float mly = gy + VOX2 * dm1;
    float mlz = gz + VOX2 * dm2;
    float mx = cza * mlx - sza * mly + p3x;
    float my = sza * mlx + cza * mly + p3y;
    float mz = mlz + p3z;

    // quat -> buggy mat4 -> Rz*M -> K -> top eigenvector (fp32 Jacobi)
    float M00, M01, M02, M10, M11, M12, M20, M21, M22;
    float nf = q0 * q0 + q1 * q1 + q2 * q2 + q3 * q3;
    if (nf < 4.76837158203125e-07f) {
        M00 = 1.f; M01 = 0.f; M02 = 0.f;
        M10 = 0.f; M11 = 1.f; M12 = 0.f;
        M20 = 0.f; M21 = 0.f; M22 = 1.f;
    } else {
        float scl = sqrtf(2.0f / nf);
        float w = q0 * scl, x = q1 * scl, y = q2 * scl, z = q3 * scl;
        M00 = 1.f - y * y - z * z;
        M01 = x * y - z * w;
        M02 = x * z + y * w;
        M10 = x * y - z * w;
        M11 = 1.f;
        M12 = y * z - x * w;
        M20 = x * z - y * w;
        M21 = y * z + x * w;
        M22 = 1.f - x * x - y * y;
    }
    float r00 = cza * M00 - sza * M10, r01 = cza * M01 - sza * M11, r02 = cza * M02 - sza * M12;
    float r10 = sza * M00 + cza * M10, r11 = sza * M01 + cza * M11, r12 = sza * M02 + cza * M12;
    float r20 = M20, r21 = M21, r22 = M22;

    float A[4][4];
    const float third = 1.0f / 3.0f;
    A[0][0] = (r00 - r11 - r22) * third;
    A[0][1] = (r01 + r10) * third;
    A[0][2] = (r02 + r20) * third;
    A[0][3] = (r21 - r12) * third;
    A[1][1] = (r11 - r00 - r22) * third;
    A[1][2] = (r12 + r21) * third;
    A[1][3] = (r02 - r20) * third;
    A[2][2] = (r22 - r00 - r11) * third;
    A[2][3] = (r10 - r01) * third;
    A[3][3] = (r00 + r11 + r22) * third;
    A[1][0] = A[0][1]; A[2][0] = A[0][2]; A[3][0] = A[0][3];
    A[2][1] = A[1][2]; A[3][1] = A[1][3]; A[3][2] = A[2][3];

    float V[4][4] = {{1, 0, 0, 0}, {0, 1, 0, 0}, {0, 0, 1, 0}, {0, 0, 0, 1}};

#define JROT(p, q)                                                              \
    {                                                                           \
        float apq = A[p][q];                                                    \
        if (fabsf(apq) > 1e-12f) {                                              \
            float theta = __fdividef(A[q][q] - A[p][p], 2.0f * apq);            \
            float tJ = __fdividef(copysignf(1.0f, theta),                       \
                                  fabsf(theta) + sqrtf(theta * theta + 1.0f));  \
            float cJ = rsqrtf(tJ * tJ + 1.0f);                                  \
            float sJ = tJ * cJ;                                                 \
            _Pragma("unroll") for (int k = 0; k < 4; k++) {                     \
                float akp = A[k][p], akq = A[k][q];                             \
                A[k][p] = cJ * akp - sJ * akq;                                  \
                A[k][q] = sJ * akp + cJ * akq;                                  \
            }                                                                   \
            _Pragma("unroll") for (int k = 0; k < 4; k++) {                     \
                float apk = A[p][k], aqk = A[q][k];                             \
                A[p][k] = cJ * apk - sJ * aqk;                                  \
                A[q][k] = sJ * apk + cJ * aqk;                                  \
            }                                                                   \
            _Pragma("unroll") for (int k = 0; k < 4; k++) {                     \
                float vkp = V[k][p], vkq = V[k][q];                             \
                V[k][p] = cJ * vkp - sJ * vkq;                                  \
                V[k][q] = sJ * vkp + cJ * vkq;                                  \
            }                                                                   \
        }                                                                       \
    }

    for (int sweep = 0; sweep < 8; sweep++) {
        float off = fabsf(A[0][1]) + fabsf(A[0][2]) + fabsf(A[0][3]) +
                    fabsf(A[1][2]) + fabsf(A[1][3]) + fabsf(A[2][3]);
        if (off < 1e-9f) break;
        JROT(0, 1) JROT(0, 2) JROT(0, 3) JROT(1, 2) JROT(1, 3) JROT(2, 3)
    }
#undef JROT

    float bd = A[0][0];
    float qx = V[0][0], qy = V[1][0], qz = V[2][0], qw = V[3][0];
#pragma unroll
    for (int k = 1; k < 4; k++) {
        bool b = A[k][k] > bd;
        bd = b ? A[k][k] : bd;
        qx = b ? V[0][k] : qx;
        qy = b ? V[1][k] : qy;
        qz = b ? V[2][k] : qz;
        qw = b ? V[3][k] : qw;
    }

    // ------- splat preprocess -------
    float qlen = sqrtf(qw * qw + qx * qx + qy * qy + qz * qz) + 1e-12f;
    float w_ = qw / qlen, x_ = qx / qlen, y_ = qy / qlen, z_ = qz / qlen;
    float Rq[3][3] = {
        {1.f - 2.f * (y_ * y_ + z_ * z_), 2.f * (x_ * y_ - w_ * z_), 2.f * (x_ * z_ + w_ * y_)},
        {2.f * (x_ * y_ + w_ * z_), 1.f - 2.f * (x_ * x_ + z_ * z_), 2.f * (y_ * z_ - w_ * x_)},
        {2.f * (x_ * z_ - w_ * y_), 2.f * (y_ * z_ + w_ * x_), 1.f - 2.f * (x_ * x_ + y_ * y_)}};
    float s2[3] = {sc0 * sc0, sc1 * sc1, sc2 * sc2};
    float cov3[3][3];
#pragma unroll
    for (int a = 0; a < 3; a++)
#pragma unroll
        for (int bb = 0; bb < 3; bb++)
            cov3[a][bb] = Rq[a][0] * s2[0] * Rq[bb][0] + Rq[a][1] * s2[1] * Rq[bb][1]
                        + Rq[a][2] * s2[2] * Rq[bb][2];

    int view = viewnum[0];
    const float* vm2 = vms + view * 16;
    float R3[3][3] = {{vm2[0], vm2[1], vm2[2]}, {vm2[4], vm2[5], vm2[6]}, {vm2[8], vm2[9], vm2[10]}};
    float camx = R3[0][0] * mx + R3[0][1] * my + R3[0][2] * mz + vm2[3];
    float camy = R3[1][0] * mx + R3[1][1] * my + R3[1][2] * mz + vm2[7];
    float camz = R3[2][0] * mx + R3[2][1] * my + R3[2][2] * mz + vm2[11];

    float tmp[3][3], covc[3][3];
#pragma unroll
    for (int a = 0; a < 3; a++)
#pragma unroll
        for (int bb = 0; bb < 3; bb++)
            tmp[a][bb] = R3[a][0] * cov3[0][bb] + R3[a][1] * cov3[1][bb] + R3[a][2] * cov3[2][bb];
#pragma unroll
    for (int a = 0; a < 3; a++)
#pragma unroll
        for (int bb = 0; bb < 3; bb++)
            covc[a][bb] = tmp[a][0] * R3[bb][0] + tmp[a][1] * R3[bb][1] + tmp[a][2] * R3[bb][2];

    const float* K2 = Ks + view * 9;
    float fx = K2[0], fy = K2[4], cxk = K2[2], cyk = K2[5];
    float rz = 1.0f / camz;
    float J00 = fx * rz, J02 = -fx * camx * rz * rz;
    float J11 = fy * rz, J12 = -fy * camy * rz * rz;
    float t0x = J00 * covc[0][0] + J02 * covc[2][0];
    float t0y = J00 * covc[0][1] + J02 * covc[2][1];
    float t0z = J00 * covc[0][2] + J02 * covc[2][2];
    float t1y = J11 * covc[1][1] + J12 * covc[2][1];
    float t1z = J11 * covc[1][2] + J12 * covc[2][2];
    float c00 = t0x * J00 + t0z * J02;
    float c01 = t0y * J11 + t0z * J12;
    float c11 = t1y * J11 + t1z * J12;

    float a2 = c00 + 0.3f;
    float b2v = c01;
    float c2 = c11 + 0.3f;
    float det = a2 * c2 - b2v * b2v;
    float det_s = (det > 1e-12f) ? det : 1.0f;
    float cca = c2 / det_s, ccb = -b2v / det_s, ccc = a2 / det_s;
    float lam = 0.5f * (a2 + c2) + sqrtf(fmaxf(0.25f * (a2 - c2) * (a2 - c2) + b2v * b2v, 1e-12f));
    float radius = ceilf(3.0f * sqrtf(lam));
    bool valid = (camz > 0.01f) && (det > 1e-12f) && (radius > 2.0f);
    float op = valid ? opac : 0.0f;
    float mux = fx * camx * rz + cxk;
    float muy = fy * camy * rz + cyk;

    float smax = -1e30f;
    float bx0 = 1e30f, bx1 = -1e30f, by0 = 1e30f, by1 = -1e30f;
    if (op * 255.0f >= 1.0f) {
        smax = logf(255.0f * op) + 1e-4f;
        float detM = cca * ccc - ccb * ccb;
        if (detM > 0.0f && smax > 0.0f) {
            float dxm = sqrtf(2.0f * smax * ccc / detM) + 0.02f;
            float dym = sqrtf(2.0f * smax * cca / detM) + 0.02f;
            bx0 = mux - dxm; bx1 = mux + dxm;
            by0 = muy - dym; by1 = muy + dym;
        } else if (smax > 0.0f) {
            bx0 = -1e30f; bx1 = 1e30f; by0 = -1e30f; by1 = 1e30f;
        }
    }
    if (ql == 0) {
        unsigned int zu = __float_as_uint(camz);
        zu = (zu & 0x80000000u) ? ~zu : (zu | 0x80000000u);
        g_keys[sp] = ((unsigned long long)zu << 32) | (unsigned)sp;
        g_posA[sp] = make_float4(mux, muy, cca, ccb);
        g_parA[sp] = make_float4(ccc, op, smax, 0.0f);
        g_colA[sp] = make_float4(col0, col1, col2, 0.0f);
        g_boxA[sp] = make_float4(bx0, bx1, by0, by1);
    }
}

// ---------------- kernel F: stable bitonic sort by z, gather sorted SoA ----------------
__global__ void kF() {
    __shared__ unsigned long long sk[NSEL];
    int t = threadIdx.x;
    sk[t] = g_keys[t];
    sk[t + 1024] = g_keys[t + 1024];
    __syncthreads();
    for (int k = 2; k <= NSEL; k <<= 1) {
        for (int j = k >> 1; j > 0; j >>= 1) {
            int idx = ((t & ~(j - 1)) << 1) | (t & (j - 1));
            int par = idx | j;
            bool up = ((idx & k) == 0);
            unsigned long long a = sk[idx], b = sk[par];
            if ((a > b) == up) { sk[idx] = b; sk[par] = a; }
            __syncthreads();
        }
    }
    for (int i = t; i < NSEL; i += 1024) {
        int src = (int)(sk[i] & 0xFFFFFFFFull);
        s_posA[i] = g_posA[src];
        s_parA[i] = g_parA[src];
        s_colA[i] = g_colA[src];
        s_boxA[i] = g_boxA[src];
    }
}

// ---------------- kernel G: tiled compositing with culling + early termination ----------------
__global__ void kG(const float* __restrict__ bg, float* __restrict__ out) {
    int tx = threadIdx.x, ty = threadIdx.y;
    int tid = ty * 16 + tx;
    int px = blockIdx.x * 16 + tx;
    int py = blockIdx.y * 16 + ty;
    float xs = px + 0.5f;
    float ysv = py + 0.5f;
    float tx0 = blockIdx.x * 16 + 0.5f - 1e-3f;
    float tx1 = blockIdx.x * 16 + 15.5f + 1e-3f;
    float ty0 = blockIdx.y * 16 + 0.5f - 1e-3f;
    float ty1 = blockIdx.y * 16 + 15.5f + 1e-3f;

    __shared__ float4 shP[256], shQ[256], shC[256];
    __shared__ int wcnt[8];

    float T = 1.0f, rr = 0.f, gg = 0.f, bb = 0.f;
    for (int base = 0; base < NSEL; base += 256) {
        int s = base + tid;
        float4 box = s_boxA[s];
        bool keep = (box.x <= tx1) && (box.y >= tx0) && (box.z <= ty1) && (box.w >= ty0);
        unsigned m = __ballot_sync(0xFFFFFFFFu, keep);
        int lane = tid & 31, wrp = tid >> 5;
        if (lane == 0) wcnt[wrp] = __popc(m);
        __syncthreads();
        int wbase = 0, cnt = 0;
#pragma unroll
        for (int i = 0; i < 8; i++) {
            if (i < wrp) wbase += wcnt[i];
            cnt += wcnt[i];
        }
        if (keep) {
            int p = wbase + __popc(m & ((1u << lane) - 1u));
            shP[p] = s_posA[s];
            shQ[p] = s_parA[s];
            shC[p] = s_colA[s];
        }
        __syncthreads();
        for (int n = 0; n < cnt; n++) {
            if (T < 1e-6f) break;
            float4 P = shP[n];
            float4 Q = shQ[n];
            float dx = xs - P.x, dy = ysv - P.y;
            float sigma = 0.5f * (P.z * dx * dx + Q.x * dy * dy) + P.w * dx * dy;
            if (sigma <= Q.z && sigma >= 0.0f) {
                float alpha = Q.y * __expf(-sigma);
                if (alpha >= (1.0f / 255.0f)) {
                    alpha = fminf(alpha, 0.999f);
                    float wgt = alpha * T;
                    float4 C = shC[n];
                    rr += wgt * C.x; gg += wgt * C.y; bb += wgt * C.z;
                    T *= (1.0f - alpha);
                }
            }
        }
        __syncthreads();
        if (__syncthreads_and(T < 1e-4f)) break;
    }
    float bgr = bg[0], bgg = bg[1], bgb = bg[2];
    int pix = py * 256 + px;
    out[pix * 3 + 0] = fminf(fmaxf(rr + T * bgr, 0.0f), 1.0f);
    out[pix * 3 + 1] = fminf(fmaxf(gg + T * bgg, 0.0f), 1.0f);
    out[pix * 3 + 2] = fminf(fmaxf(bb + T * bgb, 0.0f), 1.0f);
    out[196608 + pix] = 1.0f - T;
}

// ---------------- launch ----------------
extern "C" void kernel_launch(void* const* d_in, const int* in_sizes, int n_in,
                              void* d_out, int out_size) {
    const float* mask = (const float*)d_in[0];
    const float* img = (const float*)d_in[1];
    const float* p3d = (const float*)d_in[2];
    const float* angle = (const float*)d_in[3];
    const float* grid = (const float*)d_in[4];
    const float* Ks = (const float*)d_in[5];
    const float* vms = (const float*)d_in[6];
    const float* w1 = (const float*)d_in[7];
    const float* b1 = (const float*)d_in[8];
    const float* w2 = (const float*)d_in[9];
    const float* b2 = (const float*)d_in[10];
    const float* scale_param = (const float*)d_in[11];
    const float* bg = (const float*)d_in[12];
    const int* viewnum = (const int*)d_in[13];
    float* out = (float*)d_out;

    kA<<<NSEG, SEGSZ>>>(mask, p3d, angle, grid, Ks, vms);
    kB<<<1, 256>>>();
    kC<<<NSEG, SEGSZ>>>();
    kDE<<<NSEL / 32, 128>>>(mask, img, p3d, angle, grid, Ks, vms, scale_param, viewnum,
                            w1, b1, w2, b2);
    kF<<<1, 1024>>>();
    dim3 gb(16, 16), tb(16, 16);
    kG<<<gb, tb>>>(bg, out);
}

// round 6
// speedup vs baseline: 1.4974x; 1.4974x over previous
#include <cuda_runtime.h>
#include <cstdint>

#define NCELL 262144
#define NSEG  1024
#define SEGSZ 256
#define NSEL  2048
#define VOX2  0.005625f   /* 2 * (0.18/64) */
#define FILLC 0.45f

// ---------------- device scratch (static, no allocs) ----------------
__device__ unsigned char g_cls[NCELL];
__device__ int g_segCnt[NSEG * 8];
__device__ int g_segOff[NSEG * 8];
__device__ int g_classStart[8];
__device__ int g_idx[NSEL];
__device__ int g_done;
__device__ float g_fuse[128];   // [v*16: A(9), b(3), fx,fy,cx,cy] v=0..5; [96]=ca,[97]=sa,[98..100]=p3d
__device__ unsigned long long g_keys[NSEL];
__device__ float4 g_posA[NSEL], g_parA[NSEL], g_colA[NSEL], g_boxA[NSEL];
__device__ float4 s_posA[NSEL], s_parA[NSEL], s_colA[NSEL], s_boxA[NSEL];
__device__ float4 g_seg[8 * 65536];

__device__ __forceinline__ float sigmoidf(float x) { return 1.0f / (1.0f + expf(-x)); }

// ---------------- kPre: fused per-view projection coefficients ----------------
__global__ void kPre(const float* __restrict__ p3d, const float* __restrict__ angle,
                     const float* __restrict__ Ks, const float* __restrict__ vms) {
    if (threadIdx.x == 0) {
        float ang = angle[0];
        float ca = cosf(ang), sa = sinf(ang);
        g_fuse[96] = ca; g_fuse[97] = sa;
        g_fuse[98] = p3d[0]; g_fuse[99] = p3d[1]; g_fuse[100] = p3d[2];
        for (int v = 0; v < 6; v++) {
            const float* vm = vms + v * 16;
            float* F = g_fuse + v * 16;
            // A = R * Rz;  Rz = [[ca,-sa,0],[sa,ca,0],[0,0,1]]
            for (int r = 0; r < 3; r++) {
                float R0 = vm[r * 4 + 0], R1 = vm[r * 4 + 1], R2 = vm[r * 4 + 2];
                F[r * 3 + 0] = R0 * ca + R1 * sa;
                F[r * 3 + 1] = -R0 * sa + R1 * ca;
                F[r * 3 + 2] = R2;
                F[9 + r] = R0 * p3d[0] + R1 * p3d[1] + R2 * p3d[2] + vm[r * 4 + 3];
            }
            const float* K = Ks + v * 9;
            F[12] = K[0]; F[13] = K[4]; F[14] = K[2]; F[15] = K[5];
        }
    }
}

// ---------------- kA: per-cell projection + mask count + histogram (+ scan tail) ----------------
__global__ void kA(const float* __restrict__ mask, const float* __restrict__ grid) {
    __shared__ int hist[8];
    __shared__ float sf[101];
    __shared__ int s_last;
    int tid = threadIdx.x;
    if (tid < 8) hist[tid] = 0;
    if (tid < 101) sf[tid] = g_fuse[tid];
    __syncthreads();

    int i = blockIdx.x * SEGSZ + tid;
    float gx = grid[i * 3 + 0], gy = grid[i * 3 + 1], gz = grid[i * 3 + 2];

    int cnt = 0;
#pragma unroll
    for (int v = 0; v < 6; v++) {
        const float* F = sf + v * 16;
        float cx_ = F[0] * gx + F[1] * gy + F[2] * gz + F[9];
        float cy_ = F[3] * gx + F[4] * gy + F[5] * gz + F[10];
        float cz_ = F[6] * gx + F[7] * gy + F[8] * gz + F[11];
        float p0 = F[12] * cx_ + F[14] * cz_;
        float p1 = F[13] * cy_ + F[15] * cz_;
        float rz_ = 1.0f / cz_;
        float u = p0 * rz_;
        float w = p1 * rz_;
        if (u >= 0.f && u < 256.f && w >= 0.f && w < 256.f && cz_ > 0.01f) {
            int ui = (int)rintf(u); ui = min(max(ui, 0), 255);
            int vi = (int)rintf(w); vi = min(max(vi, 0), 255);
            int off = (v * 256 + vi) * 256 + ui;
            if (__ldg(&mask[off]) > 0.5f) cnt++;
        }
    }
    g_cls[i] = (unsigned char)cnt;

    int lane = tid & 31;
#pragma unroll
    for (int c = 0; c < 7; c++) {
        unsigned m = __ballot_sync(0xFFFFFFFFu, cnt == c);
        if (lane == 0 && m) atomicAdd(&hist[c], __popc(m));
    }
    __syncthreads();
    if (tid < 8) g_segCnt[blockIdx.x * 8 + tid] = hist[tid];

    // ---- last-block scan (former kB) ----
    __threadfence();
    if (tid == 0) s_last = (atomicAdd(&g_done, 1) == NSEG - 1);
    __syncthreads();
    if (!s_last) return;

    __shared__ int tot[8];
    int wrp = tid >> 5;
    if (wrp < 7) {
        int c = wrp;
        int carry = 0;
        for (int g = 0; g < 32; g++) {
            int s = g * 32 + lane;
            int v = g_segCnt[s * 8 + c];
            int incl = v;
#pragma unroll
            for (int d = 1; d < 32; d <<= 1) {
                int n = __shfl_up_sync(0xFFFFFFFFu, incl, d);
                if (lane >= d) incl += n;
            }
            g_segOff[s * 8 + c] = carry + incl - v;
            carry += __shfl_sync(0xFFFFFFFFu, incl, 31);
        }
        if (lane == 0) tot[c] = carry;
    }
    __syncthreads();
    if (tid == 0) {
        int start = 0;
        for (int cls = 6; cls >= 0; cls--) { g_classStart[cls] = start; start += tot[cls]; }
        g_done = 0;
    }
}

// ---------------- kC: ballot-based stable compaction ----------------
__global__ void kC() {
    __shared__ int wcc[8][8];
    int t = threadIdx.x;
    int seg = blockIdx.x;
    int i = seg * SEGSZ + t;
    int cl = g_cls[i];
    int lane = t & 31, wrp = t >> 5;
    unsigned b0 = __ballot_sync(0xFFFFFFFFu, cl == 0);
    unsigned b1 = __ballot_sync(0xFFFFFFFFu, cl == 1);
    unsigned b2 = __ballot_sync(0xFFFFFFFFu, cl == 2);
    unsigned b3 = __ballot_sync(0xFFFFFFFFu, cl == 3);
    unsigned b4 = __ballot_sync(0xFFFFFFFFu, cl == 4);
    unsigned b5 = __ballot_sync(0xFFFFFFFFu, cl == 5);
    unsigned b6 = __ballot_sync(0xFFFFFFFFu, cl == 6);
    unsigned myb = (cl == 0) ? b0 : (cl == 1) ? b1 : (cl == 2) ? b2 : (cl == 3) ? b3
                 : (cl == 4) ? b4 : (cl == 5) ? b5 : b6;
    if (lane < 7) {
        unsigned bb = (lane == 0) ? b0 : (lane == 1) ? b1 : (lane == 2) ? b2 : (lane == 3) ? b3
                    : (lane == 4) ? b4 : (lane == 5) ? b5 : b6;
        wcc[wrp][lane] = __popc(bb);
    }
    __syncthreads();
    int rank = __popc(myb & ((1u << lane) - 1u));
    for (int w = 0; w < wrp; w++) rank += wcc[w][cl];
    int pos = g_classStart[cl] + g_segOff[seg * 8 + cl] + rank;
    if (pos < NSEL) g_idx[pos] = i;
}

// ---------------- kDE: color sample + MLP + geometry (thread-per-splat) ----------------
__global__ void __launch_bounds__(64) kDE(
        const float* __restrict__ mask, const float* __restrict__ img,
        const float* __restrict__ grid, const float* __restrict__ Ks,
        const float* __restrict__ vms, const float* __restrict__ scale_param,
        const int* __restrict__ viewnum,
        const float* __restrict__ w1, const float* __restrict__ b1,
        const float* __restrict__ w2, const float* __restrict__ b2) {
    __shared__ __align__(16) float sw1t[128 * 4];
    __shared__ float sb1[128];
    __shared__ __align__(16) float sw2p[128 * 16];
    __shared__ float sb2[16];
    __shared__ float sf[101];
    int t = threadIdx.x;
    for (int k = t; k < 512; k += 64) {
        int j = k >> 2, i = k & 3;
        sw1t[k] = w1[i * 128 + j];
    }
    for (int k = t; k < 128; k += 64) sb1[k] = b1[k];
    for (int k = t; k < 1792; k += 64) {
        int j = k / 14, c = k - j * 14;
        sw2p[j * 16 + c] = w2[k];
    }
    if (t < 14) sb2[t] = b2[t];
    for (int k = t; k < 101; k += 64) sf[k] = g_fuse[k];
    __syncthreads();

    int sp = blockIdx.x * 64 + t;
    int cell = g_idx[sp];
    int cls = g_cls[cell];
    float frac = (float)cls / 6.0f;
    float f0 = 10.0f * frac - 5.0f;

    float gx = grid[cell * 3 + 0], gy = grid[cell * 3 + 1], gz = grid[cell * 3 + 2];

    // ---- color sampling (identical fused math as kA) ----
    int cntv = 0;
    float cr = 0.f, cg = 0.f, cb = 0.f;
#pragma unroll
    for (int v = 0; v < 6; v++) {
        const float* F = sf + v * 16;
        float cx_ = F[0] * gx + F[1] * gy + F[2] * gz + F[9];
        float cy_ = F[3] * gx + F[4] * gy + F[5] * gz + F[10];
        float cz_ = F[6] * gx + F[7] * gy + F[8] * gz + F[11];
        float p0 = F[12] * cx_ + F[14] * cz_;
        float p1 = F[13] * cy_ + F[15] * cz_;
        float rz_ = 1.0f / cz_;
        float u = p0 * rz_;
        float w = p1 * rz_;
        if (u >= 0.f && u < 256.f && w >= 0.f && w < 256.f && cz_ > 0.01f) {
            int ui = (int)rintf(u); ui = min(max(ui, 0), 255);
            int vi = (int)rintf(w); vi = min(max(vi, 0), 255);
            int off = (v * 256 + vi) * 256 + ui;
            if (__ldg(&mask[off]) > 0.5f) {
                cntv++;
                const float* ip = img + (size_t)off * 3;
                cr += __ldg(ip); cg += __ldg(ip + 1); cb += __ldg(ip + 2);
            }
        }
    }
    float f1, f2, f3;
    if (cntv == 6) { f1 = cr / 6.0f; f2 = cg / 6.0f; f3 = cb / 6.0f; }
    else { f1 = f2 = f3 = FILLC; }

    // ---- MLP ----
    float o14[14];
#pragma unroll
    for (int k = 0; k < 14; k++) o14[k] = sb2[k];
#pragma unroll 4
    for (int j = 0; j < 128; j++) {
        float4 wv = *(const float4*)&sw1t[j * 4];
        float acc = sb1[j] + f0 * wv.x + f1 * wv.y + f2 * wv.z + f3 * wv.w;
        float h = fmaxf(acc, 0.0f);
        const float* wr = &sw2p[j * 16];
        float4 a = *(const float4*)(wr);
        float4 b = *(const float4*)(wr + 4);
        float4 c = *(const float4*)(wr + 8);
        float2 d = *(const float2*)(wr + 12);
        o14[0] += h * a.x; o14[1] += h * a.y; o14[2] += h * a.z; o14[3] += h * a.w;
        o14[4] += h * b.x; o14[5] += h * b.y; o14[6] += h * b.z; o14[7] += h * b.w;
        o14[8] += h * c.x; o14[9] += h * c.y; o14[10] += h * c.z; o14[11] += h * c.w;
        o14[12] += h * d.x; o14[13] += h * d.y;
    }

    float q0 = o14[0], q1 = o14[1], q2 = o14[2], q3 = o14[3];
    float sp0 = scale_param[0];
    float sc0 = expf(o14[4] + sp0);
    float sc1 = expf(o14[5] + sp0);
    float sc2 = expf(o14[6] + sp0);
    float col0 = fminf(fmaxf(sigmoidf(o14[8]), 0.0f), 0.99f);
    float col1 = fminf(fmaxf(sigmoidf(o14[9]), 0.0f), 0.99f);
    float col2 = fminf(fmaxf(sigmoidf(o14[10]), 0.0f), 0.99f);
    float dm0 = tanhf(o14[11]), dm1 = tanhf(o14[12]), dm2 = tanhf(o14[13]);

    float prob = sigmoidf(f0 - 0.25f);
    float tt = fminf(fmaxf((prob - 0.25f) / 0.75f, 0.0f), 1.0f);
    float opac = sigmoidf(tt);

    float cza = sf[96], sza = sf[97];
    float p3x = sf[98], p3y = sf[99], p3z = sf[100];
    float mlx = gx + VOX2 * dm0;
    float mly = gy + VOX2 * dm1;
    float mlz = gz + VOX2 * dm2;
    float mx = cza * mlx - sza * mly + p3x;
    float my = sza * mlx + cza * mly + p3y;
    float mz = mlz + p3z;

    // quat -> buggy mat4 -> Rz*M -> K -> top eigenvector (fp32 Jacobi)
    float M00, M01, M02, M10, M11, M12, M20, M21, M22;
    float nf = q0 * q0 + q1 * q1 + q2 * q2 + q3 * q3;
    if (nf < 4.76837158203125e-07f) {
        M00 = 1.f; M01 = 0.f; M02 = 0.f;
        M10 = 0.f; M11 = 1.f; M12 = 0.f;
        M20 = 0.f; M21 = 0.f; M22 = 1.f;
    } else {
        float scl = sqrtf(2.0f / nf);
        float w = q0 * scl, x = q1 * scl, y = q2 * scl, z = q3 * scl;
        M00 = 1.f - y * y - z * z;
        M01 = x * y - z * w;
        M02 = x * z + y * w;
        M10 = x * y - z * w;
        M11 = 1.f;
        M12 = y * z - x * w;
        M20 = x * z - y * w;
        M21 = y * z + x * w;
        M22 = 1.f - x * x - y * y;
    }
    float r00 = cza * M00 - sza * M10, r01 = cza * M01 - sza * M11, r02 = cza * M02 - sza * M12;
    float r10 = sza * M00 + cza * M10, r11 = sza * M01 + cza * M11, r12 = sza * M02 + cza * M12;
    float r20 = M20, r21 = M21, r22 = M22;

    float A[4][4];
    const float third = 1.0f / 3.0f;
    A[0][0] = (r00 - r11 - r22) * third;
    A[0][1] = (r01 + r10) * third;
    A[0][2] = (r02 + r20) * third;
    A[0][3] = (r21 - r12) * third;
    A[1][1] = (r11 - r00 - r22) * third;
    A[1][2] = (r12 + r21) * third;
    A[1][3] = (r02 - r20) * third;
    A[2][2] = (r22 - r00 - r11) * third;
    A[2][3] = (r10 - r01) * third;
    A[3][3] = (r00 + r11 + r22) * third;
    A[1][0] = A[0][1]; A[2][0] = A[0][2]; A[3][0] = A[0][3];
    A[2][1] = A[1][2]; A[3][1] = A[1][3]; A[3][2] = A[2][3];

    float V[4][4] = {{1, 0, 0, 0}, {0, 1, 0, 0}, {0, 0, 1, 0}, {0, 0, 0, 1}};

#define JROT(p, q)                                                              \
    {                                                                           \
        float apq = A[p][q];                                                    \
        if (fabsf(apq) > 1e-12f) {                                              \
            float theta = __fdividef(A[q][q] - A[p][p], 2.0f * apq);            \
            float tJ = __fdividef(copysignf(1.0f, theta),                       \
                                  fabsf(theta) + sqrtf(theta * theta + 1.0f));  \
            float cJ = rsqrtf(tJ * tJ + 1.0f);                                  \
            float sJ = tJ * cJ;                                                 \
            _Pragma("unroll") for (int k = 0; k < 4; k++) {                     \
                float akp = A[k][p], akq = A[k][q];                             \
                A[k][p] = cJ * akp - sJ * akq;                                  \
                A[k][q] = sJ * akp + cJ * akq;                                  \
            }                                                                   \
            _Pragma("unroll") for (int k = 0; k < 4; k++) {                     \
                float apk = A[p][k], aqk = A[q][k];                             \
                A[p][k] = cJ * apk - sJ * aqk;                                  \
                A[q][k] = sJ * apk + cJ * aqk;                                  \
            }                                                                   \
            _Pragma("unroll") for (int k = 0; k < 4; k++) {                     \
                float vkp = V[k][p], vkq = V[k][q];                             \
                V[k][p] = cJ * vkp - sJ * vkq;                                  \
                V[k][q] = sJ * vkp + cJ * vkq;                                  \
            }                                                                   \
        }                                                                       \
    }

    for (int sweep = 0; sweep < 8; sweep++) {
        float off = fabsf(A[0][1]) + fabsf(A[0][2]) + fabsf(A[0][3]) +
                    fabsf(A[1][2]) + fabsf(A[1][3]) + fabsf(A[2][3]);
        if (off < 1e-9f) break;
        JROT(0, 1) JROT(0, 2) JROT(0, 3) JROT(1, 2) JROT(1, 3) JROT(2, 3)
    }
#undef JROT

    float bd = A[0][0];
    float qx = V[0][0], qy = V[1][0], qz = V[2][0], qw = V[3][0];
#pragma unroll
    for (int k = 1; k < 4; k++) {
        bool b = A[k][k] > bd;
        bd = b ? A[k][k] : bd;
        qx = b ? V[0][k] : qx;
        qy = b ? V[1][k] : qy;
        qz = b ? V[2][k] : qz;
        qw = b ? V[3][k] : qw;
    }

    // ------- splat preprocess -------
    float qlen = sqrtf(qw * qw + qx * qx + qy * qy + qz * qz) + 1e-12f;
    float w_ = qw / qlen, x_ = qx / qlen, y_ = qy / qlen, z_ = qz / qlen;
    float Rq[3][3] = {
        {1.f - 2.f * (y_ * y_ + z_ * z_), 2.f * (x_ * y_ - w_ * z_), 2.f * (x_ * z_ + w_ * y_)},
        {2.f * (x_ * y_ + w_ * z_), 1.f - 2.f * (x_ * x_ + z_ * z_), 2.f * (y_ * z_ - w_ * x_)},
        {2.f * (x_ * z_ - w_ * y_), 2.f * (y_ * z_ + w_ * x_), 1.f - 2.f * (x_ * x_ + y_ * y_)}};
    float s2[3] = {sc0 * sc0, sc1 * sc1, sc2 * sc2};
    float cov3[3][3];
#pragma unroll
    for (int a = 0; a < 3; a++)
#pragma unroll
        for (int bb = 0; bb < 3; bb++)
            cov3[a][bb] = Rq[a][0] * s2[0] * Rq[bb][0] + Rq[a][1] * s2[1] * Rq[bb][1]
                        + Rq[a][2] * s2[2] * Rq[bb][2];

    int view = viewnum[0];
    const float* vm2 = vms + view * 16;
    float R3[3][3] = {{vm2[0], vm2[1], vm2[2]}, {vm2[4], vm2[5], vm2[6]}, {vm2[8], vm2[9], vm2[10]}};
    float camx = R3[0][0] * mx + R3[0][1] * my + R3[0][2] * mz + vm2[3];
    float camy = R3[1][0] * mx + R3[1][1] * my + R3[1][2] * mz + vm2[7];
    float camz = R3[2][0] * mx + R3[2][1] * my + R3[2][2] * mz + vm2[11];

    float tmp[3][3], covc[3][3];
#pragma unroll
    for (int a = 0; a < 3; a++)
#pragma unroll
        for (int bb = 0; bb < 3; bb++)
            tmp[a][bb] = R3[a][0] * cov3[0][bb] + R3[a][1] * cov3[1][bb] + R3[a][2] * cov3[2][bb];
#pragma unroll
    for (int a = 0; a < 3; a++)
#pragma unroll
        for (int bb = 0; bb < 3; bb++)
            covc[a][bb] = tmp[a][0] * R3[bb][0] + tmp[a][1] * R3[bb][1] + tmp[a][2] * R3[bb][2];

    const float* K2 = Ks + view * 9;
    float fx = K2[0], fy = K2[4], cxk = K2[2], cyk = K2[5];
    float rz = 1.0f / camz;
    float J00 = fx * rz, J02 = -fx * camx * rz * rz;
    float J11 = fy * rz, J12 = -fy * camy * rz * rz;
    float t0x = J00 * covc[0][0] + J02 * covc[2][0];
    float t0y = J00 * covc[0][1] + J02 * covc[2][1];
    float t0z = J00 * covc[0][2] + J02 * covc[2][2];
    float t1y = J11 * covc[1][1] + J12 * covc[2][1];
    float t1z = J11 * covc[1][2] + J12 * covc[2][2];
    float c00 = t0x * J00 + t0z * J02;
    float c01 = t0y * J11 + t0z * J12;
    float c11 = t1y * J11 + t1z * J12;

    float a2 = c00 + 0.3f;
    float b2v = c01;
    float c2 = c11 + 0.3f;
    float det = a2 * c2 - b2v * b2v;
    float det_s = (det > 1e-12f) ? det : 1.0f;
    float cca = c2 / det_s, ccb = -b2v / det_s, ccc = a2 / det_s;
    float lam = 0.5f * (a2 + c2) + sqrtf(fmaxf(0.25f * (a2 - c2) * (a2 - c2) + b2v * b2v, 1e-12f));
    float radius = ceilf(3.0f * sqrtf(lam));
    bool valid = (camz > 0.01f) && (det > 1e-12f) && (radius > 2.0f);
    float op = valid ? opac : 0.0f;
    float mux = fx * camx * rz + cxk;
    float muy = fy * camy * rz + cyk;

    unsigned int zu = __float_as_uint(camz);
    zu = (zu & 0x80000000u) ? ~zu : (zu | 0x80000000u);
    g_keys[sp] = ((unsigned long long)zu << 32) | (unsigned)sp;

    float smax = -1e30f;
    float bx0 = 1e30f, bx1 = -1e30f, by0 = 1e30f, by1 = -1e30f;
    if (op * 255.0f >= 1.0f) {
        smax = logf(255.0f * op) + 1e-4f;
        float detM = cca * ccc - ccb * ccb;
        if (detM > 0.0f && smax > 0.0f) {
            float dxm = sqrtf(2.0f * smax * ccc / detM) + 0.02f;
            float dym = sqrtf(2.0f * smax * cca / detM) + 0.02f;
            bx0 = mux - dxm; bx1 = mux + dxm;
            by0 = muy - dym; by1 = muy + dym;
        } else if (smax > 0.0f) {
            bx0 = -1e30f; bx1 = 1e30f; by0 = -1e30f; by1 = 1e30f;
        }
    }
    g_posA[sp] = make_float4(mux, muy, cca, ccb);
    g_parA[sp] = make_float4(ccc, op, smax, 0.0f);
    g_colA[sp] = make_float4(col0, col1, col2, 0.0f);
    g_boxA[sp] = make_float4(bx0, bx1, by0, by1);
}

// ---------------- kF: stable bitonic sort by z (warp-sync fast stages) ----------------
__global__ void kF() {
    __shared__ unsigned long long sk[NSEL];
    int t = threadIdx.x;
    sk[t] = g_keys[t];
    sk[t + 1024] = g_keys[t + 1024];
    __syncthreads();
    for (int k = 2; k <= NSEL; k <<= 1) {
        for (int j = k >> 1; j > 0; j >>= 1) {
            int idx = ((t & ~(j - 1)) << 1) | (t & (j - 1));
            int par = idx | j;
            bool up = ((idx & k) == 0);
            unsigned long long a = sk[idx], b = sk[par];
            if ((a > b) == up) { sk[idx] = b; sk[par] = a; }
            if (j >= 64) __syncthreads();
            else __syncwarp();
        }
        __syncthreads();
    }
    for (int i = t; i < NSEL; i += 1024) {
        int src = (int)(sk[i] & 0xFFFFFFFFull);
        s_posA[i] = g_posA[src];
        s_parA[i] = g_parA[src];
        s_colA[i] = g_colA[src];
        s_boxA[i] = g_boxA[src];
    }
}

// ---------------- kG1: per-(tile,segment) compositing ----------------
__global__ void kG1() {
    int tx = threadIdx.x, ty = threadIdx.y;
    int tid = ty * 16 + tx;
    int px = blockIdx.x * 16 + tx;
    int py = blockIdx.y * 16 + ty;
    int seg = blockIdx.z;
    float xs = px + 0.5f;
    float ysv = py + 0.5f;
    float tx0 = blockIdx.x * 16 + 0.5f - 1e-3f;
    float tx1 = blockIdx.x * 16 + 15.5f + 1e-3f;
    float ty0 = blockIdx.y * 16 + 0.5f - 1e-3f;
    float ty1 = blockIdx.y * 16 + 15.5f + 1e-3f;

    __shared__ float4 shP[256], shQ[256], shC[256];
    __shared__ int wcnt[8];

    int s = seg * 256 + tid;
    float4 box = s_boxA[s];
    bool keep = (box.x <= tx1) && (box.y >= tx0) && (box.z <= ty1) && (box.w >= ty0);
    unsigned m = __ballot_sync(0xFFFFFFFFu, keep);
    int lane = tid & 31, wrp = tid >> 5;
    if (lane == 0) wcnt[wrp] = __popc(m);
    __syncthreads();
    int wbase = 0, cnt = 0;
#pragma unroll
    for (int i = 0; i < 8; i++) {
        if (i < wrp) wbase += wcnt[i];
        cnt += wcnt[i];
    }
    if (keep) {
        int p = wbase + __popc(m & ((1u << lane) - 1u));
        shP[p] = s_posA[s];
        shQ[p] = s_parA[s];
        shC[p] = s_colA[s];
    }
    __syncthreads();

    float T = 1.0f, rr = 0.f, gg = 0.f, bb = 0.f;
    for (int n = 0; n < cnt; n++) {
        float4 P = shP[n];
        float4 Q = shQ[n];
        float dx = xs - P.x, dy = ysv - P.y;
        float sigma = 0.5f * (P.z * dx * dx + Q.x * dy * dy) + P.w * dx * dy;
        if (sigma <= Q.z && sigma >= 0.0f) {
            float alpha = Q.y * __expf(-sigma);
            if (alpha >= (1.0f / 255.0f)) {
                alpha = fminf(alpha, 0.999f);
                float wgt = alpha * T;
                float4 C = shC[n];
                rr += wgt * C.x; gg += wgt * C.y; bb += wgt * C.z;
                T *= (1.0f - alpha);
                if (T < 1e-7f) break;
            }
        }
    }
    g_seg[seg * 65536 + py * 256 + px] = make_float4(rr, gg, bb, T);
}

// ---------------- kG2: combine segments + background ----------------
__global__ void kG2(const float* __restrict__ bg, float* __restrict__ out) {
    int pix = blockIdx.x * 256 + threadIdx.x;
    float T = 1.0f, rr = 0.f, gg = 0.f, bb = 0.f;
#pragma unroll
    for (int z = 0; z < 8; z++) {
        float4 sgm = g_seg[z * 65536 + pix];
        rr += T * sgm.x; gg += T * sgm.y; bb += T * sgm.z;
        T *= sgm.w;
    }
    float bgr = bg[0], bgg = bg[1], bgb = bg[2];
    out[pix * 3 + 0] = fminf(fmaxf(rr + T * bgr, 0.0f), 1.0f);
    out[pix * 3 + 1] = fminf(fmaxf(gg + T * bgg, 0.0f), 1.0f);
    out[pix * 3 + 2] = fminf(fmaxf(bb + T * bgb, 0.0f), 1.0f);
    out[196608 + pix] = 1.0f - T;
}

// ---------------- launch ----------------
extern "C" void kernel_launch(void* const* d_in, const int* in_sizes, int n_in,
                              void* d_out, int out_size) {
    const float* mask = (const float*)d_in[0];
    const float* img = (const float*)d_in[1];
    const float* p3d = (const float*)d_in[2];
    const float* angle = (const float*)d_in[3];
    const float* grid = (const float*)d_in[4];
    const float* Ks = (const float*)d_in[5];
    const float* vms = (const float*)d_in[6];
    const float* w1 = (const float*)d_in[7];
    const float* b1 = (const float*)d_in[8];
    const float* w2 = (const float*)d_in[9];
    const float* b2 = (const float*)d_in[10];
    const float* scale_param = (const float*)d_in[11];
    const float* bg = (const float*)d_in[12];
    const int* viewnum = (const int*)d_in[13];
    float* out = (float*)d_out;

    kPre<<<1, 32>>>(p3d, angle, Ks, vms);
    kA<<<NSEG, SEGSZ>>>(mask, grid);
    kC<<<NSEG, SEGSZ>>>();
    kDE<<<NSEL / 64, 64>>>(mask, img, grid, Ks, vms, scale_param, viewnum, w1, b1, w2, b2);
    kF<<<1, 1024>>>();
    dim3 gb1(16, 16, 8), tb1(16, 16);
    kG1<<<gb1, tb1>>>();
    kG2<<<256, 256>>>(bg, out);
}

// round 7
// speedup vs baseline: 1.5337x; 1.0242x over previous
#include <cuda_runtime.h>
#include <cstdint>

#define NCELL 262144
#define NSEG  1024
#define SEGSZ 256
#define NSEL  2048
#define VOX2  0.005625f   /* 2 * (0.18/64) */
#define FILLC 0.45f

// ---------------- device scratch (static, no allocs) ----------------
__device__ unsigned char g_cls[NCELL];
__device__ int g_segCnt[NSEG * 8];
__device__ int g_segOff[NSEG * 8];
__device__ int g_classStart[8];
__device__ int g_idx[NSEL];
__device__ int g_done;
__device__ float g_fuse[128];   // [v*16: A(9), b(3), fx,fy,cx,cy] v=0..5; [96]=ca,[97]=sa,[98..100]=p3d
__device__ float g_o14[NSEL * 16];
__device__ unsigned long long g_keys[NSEL];
__device__ float4 g_posA[NSEL], g_parA[NSEL], g_colA[NSEL], g_boxA[NSEL];
__device__ float4 s_posA[NSEL], s_parA[NSEL], s_colA[NSEL], s_boxA[NSEL];
__device__ float4 g_seg[8 * 65536];

__device__ __forceinline__ float sigmoidf(float x) { return 1.0f / (1.0f + expf(-x)); }

// ---------------- kPre: fused per-view projection coefficients ----------------
__global__ void kPre(const float* __restrict__ p3d, const float* __restrict__ angle,
                     const float* __restrict__ Ks, const float* __restrict__ vms) {
    if (threadIdx.x == 0) {
        float ang = angle[0];
        float ca = cosf(ang), sa = sinf(ang);
        g_fuse[96] = ca; g_fuse[97] = sa;
        g_fuse[98] = p3d[0]; g_fuse[99] = p3d[1]; g_fuse[100] = p3d[2];
        for (int v = 0; v < 6; v++) {
            const float* vm = vms + v * 16;
            float* F = g_fuse + v * 16;
            for (int r = 0; r < 3; r++) {
                float R0 = vm[r * 4 + 0], R1 = vm[r * 4 + 1], R2 = vm[r * 4 + 2];
                F[r * 3 + 0] = R0 * ca + R1 * sa;
                F[r * 3 + 1] = -R0 * sa + R1 * ca;
                F[r * 3 + 2] = R2;
                F[9 + r] = R0 * p3d[0] + R1 * p3d[1] + R2 * p3d[2] + vm[r * 4 + 3];
            }
            const float* K = Ks + v * 9;
            F[12] = K[0]; F[13] = K[4]; F[14] = K[2]; F[15] = K[5];
        }
    }
}

// ---------------- kA: per-cell projection + mask count + histogram (+ scan tail) ----------------
__global__ void kA(const float* __restrict__ mask, const float* __restrict__ grid) {
    __shared__ int hist[8];
    __shared__ float sf[101];
    __shared__ int s_last;
    int tid = threadIdx.x;
    if (tid < 8) hist[tid] = 0;
    if (tid < 101) sf[tid] = g_fuse[tid];
    __syncthreads();

    int i = blockIdx.x * SEGSZ + tid;
    float gx = grid[i * 3 + 0], gy = grid[i * 3 + 1], gz = grid[i * 3 + 2];

    int cnt = 0;
#pragma unroll
    for (int v = 0; v < 6; v++) {
        const float* F = sf + v * 16;
        float cx_ = F[0] * gx + F[1] * gy + F[2] * gz + F[9];
        float cy_ = F[3] * gx + F[4] * gy + F[5] * gz + F[10];
        float cz_ = F[6] * gx + F[7] * gy + F[8] * gz + F[11];
        float p0 = F[12] * cx_ + F[14] * cz_;
        float p1 = F[13] * cy_ + F[15] * cz_;
        float rz_ = 1.0f / cz_;
        float u = p0 * rz_;
        float w = p1 * rz_;
        if (u >= 0.f && u < 256.f && w >= 0.f && w < 256.f && cz_ > 0.01f) {
            int ui = (int)rintf(u); ui = min(max(ui, 0), 255);
            int vi = (int)rintf(w); vi = min(max(vi, 0), 255);
            int off = (v * 256 + vi) * 256 + ui;
            if (__ldg(&mask[off]) > 0.5f) cnt++;
        }
    }
    g_cls[i] = (unsigned char)cnt;

    int lane = tid & 31;
#pragma unroll
    for (int c = 0; c < 7; c++) {
        unsigned m = __ballot_sync(0xFFFFFFFFu, cnt == c);
        if (lane == 0 && m) atomicAdd(&hist[c], __popc(m));
    }
    __syncthreads();
    if (tid < 8) g_segCnt[blockIdx.x * 8 + tid] = hist[tid];

    // ---- last-block scan ----
    __threadfence();
    if (tid == 0) s_last = (atomicAdd(&g_done, 1) == NSEG - 1);
    __syncthreads();
    if (!s_last) return;

    __shared__ int tot[8];
    int wrp = tid >> 5;
    if (wrp < 7) {
        int c = wrp;
        int carry = 0;
        for (int g = 0; g < 32; g++) {
            int s = g * 32 + lane;
            int v = g_segCnt[s * 8 + c];
            int incl = v;
#pragma unroll
            for (int d = 1; d < 32; d <<= 1) {
                int n = __shfl_up_sync(0xFFFFFFFFu, incl, d);
                if (lane >= d) incl += n;
            }
            g_segOff[s * 8 + c] = carry + incl - v;
            carry += __shfl_sync(0xFFFFFFFFu, incl, 31);
        }
        if (lane == 0) tot[c] = carry;
    }
    __syncthreads();
    if (tid == 0) {
        int start = 0;
        for (int cls = 6; cls >= 0; cls--) { g_classStart[cls] = start; start += tot[cls]; }
        g_done = 0;
    }
}

// ---------------- kC: ballot-based stable compaction ----------------
__global__ void kC() {
    __shared__ int wcc[8][8];
    int t = threadIdx.x;
    int seg = blockIdx.x;
    int i = seg * SEGSZ + t;
    int cl = g_cls[i];
    int lane = t & 31, wrp = t >> 5;
    unsigned b0 = __ballot_sync(0xFFFFFFFFu, cl == 0);
    unsigned b1 = __ballot_sync(0xFFFFFFFFu, cl == 1);
    unsigned b2 = __ballot_sync(0xFFFFFFFFu, cl == 2);
    unsigned b3 = __ballot_sync(0xFFFFFFFFu, cl == 3);
    unsigned b4 = __ballot_sync(0xFFFFFFFFu, cl == 4);
    unsigned b5 = __ballot_sync(0xFFFFFFFFu, cl == 5);
    unsigned b6 = __ballot_sync(0xFFFFFFFFu, cl == 6);
    unsigned myb = (cl == 0) ? b0 : (cl == 1) ? b1 : (cl == 2) ? b2 : (cl == 3) ? b3
                 : (cl == 4) ? b4 : (cl == 5) ? b5 : b6;
    if (lane < 7) {
        unsigned bb = (lane == 0) ? b0 : (lane == 1) ? b1 : (lane == 2) ? b2 : (lane == 3) ? b3
                    : (lane == 4) ? b4 : (lane == 5) ? b5 : b6;
        wcc[wrp][lane] = __popc(bb);
    }
    __syncthreads();
    int rank = __popc(myb & ((1u << lane) - 1u));
    for (int w = 0; w < wrp; w++) rank += wcc[w][cl];
    int pos = g_classStart[cl] + g_segOff[seg * 8 + cl] + rank;
    if (pos < NSEL) g_idx[pos] = i;
}

// ---------------- kCol: color sample + MLP (4 lanes per splat) ----------------
__global__ void __launch_bounds__(128) kCol(
        const float* __restrict__ mask, const float* __restrict__ img,
        const float* __restrict__ grid,
        const float* __restrict__ w1, const float* __restrict__ b1,
        const float* __restrict__ w2, const float* __restrict__ b2) {
    __shared__ __align__(16) float sw1t[128 * 4];   // [j][i] transposed w1 rows 0..3
    __shared__ float sb1[128];
    __shared__ __align__(16) float sw2p[128 * 20];  // [j][0..13] stride 20 (conflict-free quads)
    __shared__ float sb2[16];
    __shared__ float sf[101];
    int t = threadIdx.x;
    for (int k = t; k < 512; k += 128) {
        int j = k >> 2, i = k & 3;
        sw1t[k] = w1[i * 128 + j];
    }
    if (t < 128) sb1[t] = b1[t];
    for (int k = t; k < 1792; k += 128) {
        int j = k / 14, c = k - j * 14;
        sw2p[j * 20 + c] = w2[k];
    }
    if (t < 14) sb2[t] = b2[t];
    if (t >= 16 && t < 117) sf[t - 16] = g_fuse[t - 16];
    __syncthreads();

    int quad = t >> 2;   // 0..31
    int ql = t & 3;
    int sp = blockIdx.x * 32 + quad;
    int cell = g_idx[sp];
    int cls = g_cls[cell];
    float frac = (float)cls / 6.0f;
    float f0 = 10.0f * frac - 5.0f;

    float gx = grid[cell * 3 + 0], gy = grid[cell * 3 + 1], gz = grid[cell * 3 + 2];

    // ---- lane-split color sampling: lane ql samples views {ql} and (ql<2 ? {ql+4} : {}) ----
    int cntv = 0;
    float cr = 0.f, cg = 0.f, cb = 0.f;
#pragma unroll
    for (int rep = 0; rep < 2; rep++) {
        int v = ql + rep * 4;
        if (v < 6) {
            const float* F = sf + v * 16;
            float cx_ = F[0] * gx + F[1] * gy + F[2] * gz + F[9];
            float cy_ = F[3] * gx + F[4] * gy + F[5] * gz + F[10];
            float cz_ = F[6] * gx + F[7] * gy + F[8] * gz + F[11];
            float p0 = F[12] * cx_ + F[14] * cz_;
            float p1 = F[13] * cy_ + F[15] * cz_;
            float rz_ = 1.0f / cz_;
            float u = p0 * rz_;
            float w = p1 * rz_;
            if (u >= 0.f && u < 256.f && w >= 0.f && w < 256.f && cz_ > 0.01f) {
                int ui = (int)rintf(u); ui = min(max(ui, 0), 255);
                int vi = (int)rintf(w); vi = min(max(vi, 0), 255);
                int off = (v * 256 + vi) * 256 + ui;
                if (__ldg(&mask[off]) > 0.5f) {
                    cntv++;
                    const float* ip = img + (size_t)off * 3;
                    cr += __ldg(ip); cg += __ldg(ip + 1); cb += __ldg(ip + 2);
                }
            }
        }
    }
    // reduce over 4 lanes of the quad
    cntv += __shfl_xor_sync(0xFFFFFFFFu, cntv, 1);
    cntv += __shfl_xor_sync(0xFFFFFFFFu, cntv, 2);
    cr += __shfl_xor_sync(0xFFFFFFFFu, cr, 1);
    cr += __shfl_xor_sync(0xFFFFFFFFu, cr, 2);
    cg += __shfl_xor_sync(0xFFFFFFFFu, cg, 1);
    cg += __shfl_xor_sync(0xFFFFFFFFu, cg, 2);
    cb += __shfl_xor_sync(0xFFFFFFFFu, cb, 1);
    cb += __shfl_xor_sync(0xFFFFFFFFu, cb, 2);
    float f1, f2, f3;
    if (cntv == 6) { f1 = cr / 6.0f; f2 = cg / 6.0f; f3 = cb / 6.0f; }
    else { f1 = f2 = f3 = FILLC; }

    // ---- quad-parallel MLP: lane ql handles hidden units j = ql + 4*i ----
    float o14[14];
#pragma unroll
    for (int k = 0; k < 14; k++) o14[k] = 0.0f;
#pragma unroll 8
    for (int i = 0; i < 32; i++) {
        int j = ql + (i << 2);
        float4 wv = *(const float4*)&sw1t[j * 4];
        float acc = sb1[j] + f0 * wv.x + f1 * wv.y + f2 * wv.z + f3 * wv.w;
        float h = fmaxf(acc, 0.0f);
        const float* wr = &sw2p[j * 20];
        float4 a = *(const float4*)(wr);
        float4 b = *(const float4*)(wr + 4);
        float4 c = *(const float4*)(wr + 8);
        float2 d = *(const float2*)(wr + 12);
        o14[0] += h * a.x; o14[1] += h * a.y; o14[2] += h * a.z; o14[3] += h * a.w;
        o14[4] += h * b.x; o14[5] += h * b.y; o14[6] += h * b.z; o14[7] += h * b.w;
        o14[8] += h * c.x; o14[9] += h * c.y; o14[10] += h * c.z; o14[11] += h * c.w;
        o14[12] += h * d.x; o14[13] += h * d.y;
    }
#pragma unroll
    for (int k = 0; k < 14; k++) {
        o14[k] += __shfl_xor_sync(0xFFFFFFFFu, o14[k], 1);
        o14[k] += __shfl_xor_sync(0xFFFFFFFFu, o14[k], 2);
        o14[k] += sb2[k];
    }
    // quad-strided float4 writes (lane ql writes elements 4*ql..4*ql+3)
    float4 wv4;
    int kb = ql * 4;
    wv4.x = (kb + 0 < 14) ? o14[kb + 0] : 0.0f;
    wv4.y = (kb + 1 < 14) ? o14[kb + 1] : 0.0f;
    wv4.z = (kb + 2 < 14) ? o14[kb + 2] : 0.0f;
    wv4.w = (kb + 3 < 14) ? o14[kb + 3] : 0.0f;
    *(float4*)&g_o14[sp * 16 + kb] = wv4;
}

// ---------------- kGeo: activations + Jacobi + splat preprocess ----------------
__global__ void __launch_bounds__(256) kGeo(
        const float* __restrict__ grid, const float* __restrict__ Ks,
        const float* __restrict__ vms, const float* __restrict__ scale_param,
        const int* __restrict__ viewnum) {
    int sp = blockIdx.x * 256 + threadIdx.x;
    int cell = g_idx[sp];
    int cls = g_cls[cell];
    float frac = (float)cls / 6.0f;
    float f0 = 10.0f * frac - 5.0f;

    float o14[14];
    {
        float4 a = *(const float4*)&g_o14[sp * 16 + 0];
        float4 b = *(const float4*)&g_o14[sp * 16 + 4];
        float4 c = *(const float4*)&g_o14[sp * 16 + 8];
        float4 d = *(const float4*)&g_o14[sp * 16 + 12];
        o14[0] = a.x; o14[1] = a.y; o14[2] = a.z; o14[3] = a.w;
        o14[4] = b.x; o14[5] = b.y; o14[6] = b.z; o14[7] = b.w;
        o14[8] = c.x; o14[9] = c.y; o14[10] = c.z; o14[11] = c.w;
        o14[12] = d.x; o14[13] = d.y;
    }

    float q0 = o14[0], q1 = o14[1], q2 = o14[2], q3 = o14[3];
    float sp0 = scale_param[0];
    float sc0 = expf(o14[4] + sp0);
    float sc1 = expf(o14[5] + sp0);
    float sc2 = expf(o14[6] + sp0);
    float col0 = fminf(fmaxf(sigmoidf(o14[8]), 0.0f), 0.99f);
    float col1 = fminf(fmaxf(sigmoidf(o14[9]), 0.0f), 0.99f);
    float col2 = fminf(fmaxf(sigmoidf(o14[10]), 0.0f), 0.99f);
    float dm0 = tanhf(o14[11]), dm1 = tanhf(o14[12]), dm2 = tanhf(o14[13]);

    float prob = sigmoidf(f0 - 0.25f);
    float tt = fminf(fmaxf((prob - 0.25f) / 0.75f, 0.0f), 1.0f);
    float opac = sigmoidf(tt);

    float cza = g_fuse[96], sza = g_fuse[97];
    float p3x = g_fuse[98], p3y = g_fuse[99], p3z = g_fuse[100];
    float gx = grid[cell * 3 + 0], gy = grid[cell * 3 + 1], gz = grid[cell * 3 + 2];
    float mlx = gx + VOX2 * dm0;
    float mly = gy + VOX2 * dm1;
    float mlz = gz + VOX2 * dm2;
    float mx = cza * mlx - sza * mly + p3x;
    float my = sza * mlx + cza * mly + p3y;
    float mz = mlz + p3z;

    float M00, M01, M02, M10, M11, M12, M20, M21, M22;
    float nf = q0 * q0 + q1 * q1 + q2 * q2 + q3 * q3;
    if (nf < 4.76837158203125e-07f) {
        M00 = 1.f; M01 = 0.f; M02 = 0.f;
        M10 = 0.f; M11 = 1.f; M12 = 0.f;
        M20 = 0.f; M21 = 0.f; M22 = 1.f;
    } else {
        float scl = sqrtf(2.0f / nf);
        float w = q0 * scl, x = q1 * scl, y = q2 * scl, z = q3 * scl;
        M00 = 1.f - y * y - z * z;
        M01 = x * y - z * w;
        M02 = x * z + y * w;
        M10 = x * y - z * w;
        M11 = 1.f;
        M12 = y * z - x * w;
        M20 = x * z - y * w;
        M21 = y * z + x * w;
        M22 = 1.f - x * x - y * y;
    }
    float r00 = cza * M00 - sza * M10, r01 = cza * M01 - sza * M11, r02 = cza * M02 - sza * M12;
    float r10 = sza * M00 + cza * M10, r11 = sza * M01 + cza * M11, r12 = sza * M02 + cza * M12;
    float r20 = M20, r21 = M21, r22 = M22;

    float A[4][4];
    const float third = 1.0f / 3.0f;
    A[0][0] = (r00 - r11 - r22) * third;
    A[0][1] = (r01 + r10) * third;
    A[0][2] = (r02 + r20) * third;
    A[0][3] = (r21 - r12) * third;
    A[1][1] = (r11 - r00 - r22) * third;
    A[1][2] = (r12 + r21) * third;
    A[1][3] = (r02 - r20) * third;
    A[2][2] = (r22 - r00 - r11) * third;
    A[2][3] = (r10 - r01) * third;
    A[3][3] = (r00 + r11 + r22) * third;
    A[1][0] = A[0][1]; A[2][0] = A[0][2]; A[3][0] = A[0][3];
    A[2][1] = A[1][2]; A[3][1] = A[1][3]; A[3][2] = A[2][3];

    float V[4][4] = {{1, 0, 0, 0}, {0, 1, 0, 0}, {0, 0, 1, 0}, {0, 0, 0, 1}};

#define JROT(p, q)                                                              \
    {                                                                           \
        float apq = A[p][q];                                                    \
        if (fabsf(apq) > 1e-12f) {                                              \
            float theta = __fdividef(A[q][q] - A[p][p], 2.0f * apq);            \
            float tJ = __fdividef(copysignf(1.0f, theta),                       \
                                  fabsf(theta) + sqrtf(theta * theta + 1.0f));  \
            float cJ = rsqrtf(tJ * tJ + 1.0f);                                  \
            float sJ = tJ * cJ;                                                 \
            _Pragma("unroll") for (int k = 0; k < 4; k++) {                     \
                float akp = A[k][p], akq = A[k][q];                             \
                A[k][p] = cJ * akp - sJ * akq;                                  \
                A[k][q] = sJ * akp + cJ * akq;                                  \
            }                                                                   \
            _Pragma("unroll") for (int k = 0; k < 4; k++) {                     \
                float apk = A[p][k], aqk = A[q][k];                             \
                A[p][k] = cJ * apk - sJ * aqk;                                  \
                A[q][k] = sJ * apk + cJ * aqk;                                  \
            }                                                                   \
            _Pragma("unroll") for (int k = 0; k < 4; k++) {                     \
                float vkp = V[k][p], vkq = V[k][q];                             \
                V[k][p] = cJ * vkp - sJ * vkq;                                  \
                V[k][q] = sJ * vkp + cJ * vkq;                                  \
            }                                                                   \
        }                                                                       \
    }

    for (int sweep = 0; sweep < 8; sweep++) {
        float off = fabsf(A[0][1]) + fabsf(A[0][2]) + fabsf(A[0][3]) +
                    fabsf(A[1][2]) + fabsf(A[1][3]) + fabsf(A[2][3]);
        if (off < 1e-9f) break;
        JROT(0, 1) JROT(0, 2) JROT(0, 3) JROT(1, 2) JROT(1, 3) JROT(2, 3)
    }
#undef JROT

    float bd = A[0][0];
    float qx = V[0][0], qy = V[1][0], qz = V[2][0], qw = V[3][0];
#pragma unroll
    for (int k = 1; k < 4; k++) {
        bool b = A[k][k] > bd;
        bd = b ? A[k][k] : bd;
        qx = b ? V[0][k] : qx;
        qy = b ? V[1][k] : qy;
        qz = b ? V[2][k] : qz;
        qw = b ? V[3][k] : qw;
    }

    float qlen = sqrtf(qw * qw + qx * qx + qy * qy + qz * qz) + 1e-12f;
    float w_ = qw / qlen, x_ = qx / qlen, y_ = qy / qlen, z_ = qz / qlen;
    float Rq[3][3] = {
        {1.f - 2.f * (y_ * y_ + z_ * z_), 2.f * (x_ * y_ - w_ * z_), 2.f * (x_ * z_ + w_ * y_)},
        {2.f * (x_ * y_ + w_ * z_), 1.f - 2.f * (x_ * x_ + z_ * z_), 2.f * (y_ * z_ - w_ * x_)},
        {2.f * (x_ * z_ - w_ * y_), 2.f * (y_ * z_ + w_ * x_), 1.f - 2.f * (x_ * x_ + y_ * y_)}};
    float s2[3] = {sc0 * sc0, sc1 * sc1, sc2 * sc2};
    float cov3[3][3];
#pragma unroll
    for (int a = 0; a < 3; a++)
#pragma unroll
        for (int bb = 0; bb < 3; bb++)
            cov3[a][bb] = Rq[a][0] * s2[0] * Rq[bb][0] + Rq[a][1] * s2[1] * Rq[bb][1]
                        + Rq[a][2] * s2[2] * Rq[bb][2];

    int view = viewnum[0];
    const float* vm2 = vms + view * 16;
    float R3[3][3] = {{vm2[0], vm2[1], vm2[2]}, {vm2[4], vm2[5], vm2[6]}, {vm2[8], vm2[9], vm2[10]}};
    float camx = R3[0][0] * mx + R3[0][1] * my + R3[0][2] * mz + vm2[3];
    float camy = R3[1][0] * mx + R3[1][1] * my + R3[1][2] * mz + vm2[7];
    float camz = R3[2][0] * mx + R3[2][1] * my + R3[2][2] * mz + vm2[11];

    float tmp[3][3], covc[3][3];
#pragma unroll
    for (int a = 0; a < 3; a++)
#pragma unroll
        for (int bb = 0; bb < 3; bb++)
            tmp[a][bb] = R3[a][0] * cov3[0][bb] + R3[a][1] * cov3[1][bb] + R3[a][2] * cov3[2][bb];
#pragma unroll
    for (int a = 0; a < 3; a++)
#pragma unroll
        for (int bb = 0; bb < 3; bb++)
            covc[a][bb] = tmp[a][0] * R3[bb][0] + tmp[a][1] * R3[bb][1] + tmp[a][2] * R3[bb][2];

    const float* K2 = Ks + view * 9;
    float fx = K2[0], fy = K2[4], cxk = K2[2], cyk = K2[5];
    float rz = 1.0f / camz;
    float J00 = fx * rz, J02 = -fx * camx * rz * rz;
    float J11 = fy * rz, J12 = -fy * camy * rz * rz;
    float t0x = J00 * covc[0][0] + J02 * covc[2][0];
    float t0y = J00 * covc[0][1] + J02 * covc[2][1];
    float t0z = J00 * covc[0][2] + J02 * covc[2][2];
    float t1y = J11 * covc[1][1] + J12 * covc[2][1];
    float t1z = J11 * covc[1][2] + J12 * covc[2][2];
    float c00 = t0x * J00 + t0z * J02;
    float c01 = t0y * J11 + t0z * J12;
    float c11 = t1y * J11 + t1z * J12;

    float a2 = c00 + 0.3f;
    float b2v = c01;
    float c2 = c11 + 0.3f;
    float det = a2 * c2 - b2v * b2v;
    float det_s = (det > 1e-12f) ? det : 1.0f;
    float cca = c2 / det_s, ccb = -b2v / det_s, ccc = a2 / det_s;
    float lam = 0.5f * (a2 + c2) + sqrtf(fmaxf(0.25f * (a2 - c2) * (a2 - c2) + b2v * b2v, 1e-12f));
    float radius = ceilf(3.0f * sqrtf(lam));
    bool valid = (camz > 0.01f) && (det > 1e-12f) && (radius > 2.0f);
    float op = valid ? opac : 0.0f;
    float mux = fx * camx * rz + cxk;
    float muy = fy * camy * rz + cyk;

    unsigned int zu = __float_as_uint(camz);
    zu = (zu & 0x80000000u) ? ~zu : (zu | 0x80000000u);
    g_keys[sp] = ((unsigned long long)zu << 32) | (unsigned)sp;

    float smax = -1e30f;
    float bx0 = 1e30f, bx1 = -1e30f, by0 = 1e30f, by1 = -1e30f;
    if (op * 255.0f >= 1.0f) {
        smax = logf(255.0f * op) + 1e-4f;
        float detM = cca * ccc - ccb * ccb;
        if (detM > 0.0f && smax > 0.0f) {
            float dxm = sqrtf(2.0f * smax * ccc / detM) + 0.02f;
            float dym = sqrtf(2.0f * smax * cca / detM) + 0.02f;
            bx0 = mux - dxm; bx1 = mux + dxm;
            by0 = muy - dym; by1 = muy + dym;
        } else if (smax > 0.0f) {
            bx0 = -1e30f; bx1 = 1e30f; by0 = -1e30f; by1 = 1e30f;
        }
    }
    g_posA[sp] = make_float4(mux, muy, cca, ccb);
    g_parA[sp] = make_float4(ccc, op, smax, 0.0f);
    g_colA[sp] = make_float4(col0, col1, col2, 0.0f);
    g_boxA[sp] = make_float4(bx0, bx1, by0, by1);
}

// ---------------- kF: stable bitonic sort by z (warp-sync fast stages) ----------------
__global__ void kF() {
    __shared__ unsigned long long sk[NSEL];
    int t = threadIdx.x;
    sk[t] = g_keys[t];
    sk[t + 1024] = g_keys[t + 1024];
    __syncthreads();
    for (int k = 2; k <= NSEL; k <<= 1) {
        for (int j = k >> 1; j > 0; j >>= 1) {
            int idx = ((t & ~(j - 1)) << 1) | (t & (j - 1));
            int par = idx | j;
            bool up = ((idx & k) == 0);
            unsigned long long a = sk[idx], b = sk[par];
            if ((a > b) == up) { sk[idx] = b; sk[par] = a; }
            if (j >= 64) __syncthreads();
            else __syncwarp();
        }
        __syncthreads();
    }
    for (int i = t; i < NSEL; i += 1024) {
        int src = (int)(sk[i] & 0xFFFFFFFFull);
        s_posA[i] = g_posA[src];
        s_parA[i] = g_parA[src];
        s_colA[i] = g_colA[src];
        s_boxA[i] = g_boxA[src];
    }
}

// ---------------- kG1: per-(tile,segment) compositing ----------------
__global__ void kG1() {
    int tx = threadIdx.x, ty = threadIdx.y;
    int tid = ty * 16 + tx;
    int px = blockIdx.x * 16 + tx;
    int py = blockIdx.y * 16 + ty;
    int seg = blockIdx.z;
    float xs = px + 0.5f;
    float ysv = py + 0.5f;
    float tx0 = blockIdx.x * 16 + 0.5f - 1e-3f;
    float tx1 = blockIdx.x * 16 + 15.5f + 1e-3f;
    float ty0 = blockIdx.y * 16 + 0.5f - 1e-3f;
    float ty1 = blockIdx.y * 16 + 15.5f + 1e-3f;

    __shared__ float4 shP[256], shQ[256], shC[256];
    __shared__ int wcnt[8];

    int s = seg * 256 + tid;
    float4 box = s_boxA[s];
    bool keep = (box.x <= tx1) && (box.y >= tx0) && (box.z <= ty1) && (box.w >= ty0);
    unsigned m = __ballot_sync(0xFFFFFFFFu, keep);
    int lane = tid & 31, wrp = tid >> 5;
    if (lane == 0) wcnt[wrp] = __popc(m);
    __syncthreads();
    int wbase = 0, cnt = 0;
#pragma unroll
    for (int i = 0; i < 8; i++) {
        if (i < wrp) wbase += wcnt[i];
        cnt += wcnt[i];
    }
    if (keep) {
        int p = wbase + __popc(m & ((1u << lane) - 1u));
        shP[p] = s_posA[s];
        shQ[p] = s_parA[s];
        shC[p] = s_colA[s];
    }
    __syncthreads();

    float T = 1.0f, rr = 0.f, gg = 0.f, bb = 0.f;
    for (int n = 0; n < cnt; n++) {
        float4 P = shP[n];
        float4 Q = shQ[n];
        float dx = xs - P.x, dy = ysv - P.y;
        float sigma = 0.5f * (P.z * dx * dx + Q.x * dy * dy) + P.w * dx * dy;
        if (sigma <= Q.z && sigma >= 0.0f) {
            float alpha = Q.y * __expf(-sigma);
            if (alpha >= (1.0f / 255.0f)) {
                alpha = fminf(alpha, 0.999f);
                float wgt = alpha * T;
                float4 C = shC[n];
                rr += wgt * C.x; gg += wgt * C.y; bb += wgt * C.z;
                T *= (1.0f - alpha);
                if (T < 1e-7f) break;
            }
        }
    }
    g_seg[seg * 65536 + py * 256 + px] = make_float4(rr, gg, bb, T);
}

// ---------------- kG2: combine segments + background ----------------
__global__ void kG2(const float* __restrict__ bg, float* __restrict__ out) {
    int pix = blockIdx.x * 256 + threadIdx.x;
    float T = 1.0f, rr = 0.f, gg = 0.f, bb = 0.f;
#pragma unroll
    for (int z = 0; z < 8; z++) {
        float4 sgm = g_seg[z * 65536 + pix];
        rr += T * sgm.x; gg += T * sgm.y; bb += T * sgm.z;
        T *= sgm.w;
    }
    float bgr = bg[0], bgg = bg[1], bgb = bg[2];
    out[pix * 3 + 0] = fminf(fmaxf(rr + T * bgr, 0.0f), 1.0f);
    out[pix * 3 + 1] = fminf(fmaxf(gg + T * bgg, 0.0f), 1.0f);
    out[pix * 3 + 2] = fminf(fmaxf(bb + T * bgb, 0.0f), 1.0f);
    out[196608 + pix] = 1.0f - T;
}

// ---------------- launch ----------------
extern "C" void kernel_launch(void* const* d_in, const int* in_sizes, int n_in,
                              void* d_out, int out_size) {
    const float* mask = (const float*)d_in[0];
    const float* img = (const float*)d_in[1];
    const float* p3d = (const float*)d_in[2];
    const float* angle = (const float*)d_in[3];
    const float* grid = (const float*)d_in[4];
    const float* Ks = (const float*)d_in[5];
    const float* vms = (const float*)d_in[6];
    const float* w1 = (const float*)d_in[7];
    const float* b1 = (const float*)d_in[8];
    const float* w2 = (const float*)d_in[9];
    const float* b2 = (const float*)d_in[10];
    const float* scale_param = (const float*)d_in[11];
    const float* bg = (const float*)d_in[12];
    const int* viewnum = (const int*)d_in[13];
    float* out = (float*)d_out;

    kPre<<<1, 32>>>(p3d, angle, Ks, vms);
    kA<<<NSEG, SEGSZ>>>(mask, grid);
    kC<<<NSEG, SEGSZ>>>();
    kCol<<<NSEL / 32, 128>>>(mask, img, grid, w1, b1, w2, b2);
    kGeo<<<NSEL / 256, 256>>>(grid, Ks, vms, scale_param, viewnum);
    kF<<<1, 1024>>>();
    dim3 gb1(16, 16, 8), tb1(16, 16);
    kG1<<<gb1, tb1>>>();
    kG2<<<256, 256>>>(bg, out);
}

// round 8
// speedup vs baseline: 1.6333x; 1.0649x over previous
#include <cuda_runtime.h>
#include <cstdint>

#define NCELL 262144
#define NSEG  1024
#define SEGSZ 256
#define NSEL  2048
#define VOX2  0.005625f   /* 2 * (0.18/64) */
#define FILLC 0.45f

// ---------------- device scratch (static, no allocs) ----------------
__device__ unsigned char g_cls[NCELL];
__device__ int g_segCnt[NSEG * 8];
__device__ int g_segOff[NSEG * 8];
__device__ int g_classStart[8];
__device__ int g_idx[NSEL];
__device__ int g_done;
__device__ float g_fuse[128];
__device__ float g_o14[NSEL * 16];
__device__ unsigned long long g_keys[NSEL];
__device__ int g_perm[NSEL];
__device__ float4 g_posA[NSEL], g_parA[NSEL], g_colA[NSEL], g_boxA[NSEL];
__device__ float4 g_seg[8 * 65536];

__device__ __forceinline__ float sigmoidf(float x) { return 1.0f / (1.0f + expf(-x)); }

// ---------------- kA: fuse-coeff init + projection + mask count + histogram + scan tail ----------------
__global__ void kA(const float* __restrict__ mask, const float* __restrict__ grid,
                   const float* __restrict__ p3d, const float* __restrict__ angle,
                   const float* __restrict__ Ks, const float* __restrict__ vms) {
    __shared__ int hist[8];
    __shared__ float sf[101];
    __shared__ int s_last;
    int tid = threadIdx.x;
    if (tid < 8) hist[tid] = 0;
    if (tid < 6) {
        int v = tid;
        float ang = angle[0];
        float ca = cosf(ang), sa = sinf(ang);
        const float* vm = vms + v * 16;
        float* F = sf + v * 16;
        for (int r = 0; r < 3; r++) {
            float R0 = vm[r * 4 + 0], R1 = vm[r * 4 + 1], R2 = vm[r * 4 + 2];
            F[r * 3 + 0] = R0 * ca + R1 * sa;
            F[r * 3 + 1] = -R0 * sa + R1 * ca;
            F[r * 3 + 2] = R2;
            F[9 + r] = R0 * p3d[0] + R1 * p3d[1] + R2 * p3d[2] + vm[r * 4 + 3];
        }
        const float* K = Ks + v * 9;
        F[12] = K[0]; F[13] = K[4]; F[14] = K[2]; F[15] = K[5];
    } else if (tid == 6) {
        float ang = angle[0];
        sf[96] = cosf(ang); sf[97] = sinf(ang);
        sf[98] = p3d[0]; sf[99] = p3d[1]; sf[100] = p3d[2];
    }
    __syncthreads();

    int i = blockIdx.x * SEGSZ + tid;
    float gx = grid[i * 3 + 0], gy = grid[i * 3 + 1], gz = grid[i * 3 + 2];

    int cnt = 0;
#pragma unroll
    for (int v = 0; v < 6; v++) {
        const float* F = sf + v * 16;
        float cx_ = F[0] * gx + F[1] * gy + F[2] * gz + F[9];
        float cy_ = F[3] * gx + F[4] * gy + F[5] * gz + F[10];
        float cz_ = F[6] * gx + F[7] * gy + F[8] * gz + F[11];
        float p0 = F[12] * cx_ + F[14] * cz_;
        float p1 = F[13] * cy_ + F[15] * cz_;
        float rz_ = 1.0f / cz_;
        float u = p0 * rz_;
        float w = p1 * rz_;
        if (u >= 0.f && u < 256.f && w >= 0.f && w < 256.f && cz_ > 0.01f) {
            int ui = (int)rintf(u); ui = min(max(ui, 0), 255);
            int vi = (int)rintf(w); vi = min(max(vi, 0), 255);
            int off = (v * 256 + vi) * 256 + ui;
            if (__ldg(&mask[off]) > 0.5f) cnt++;
        }
    }
    g_cls[i] = (unsigned char)cnt;

    int lane = tid & 31;
#pragma unroll
    for (int c = 0; c < 7; c++) {
        unsigned m = __ballot_sync(0xFFFFFFFFu, cnt == c);
        if (lane == 0 && m) atomicAdd(&hist[c], __popc(m));
    }
    __syncthreads();
    if (tid < 8) g_segCnt[blockIdx.x * 8 + tid] = hist[tid];
    if (blockIdx.x == 0 && tid < 101) g_fuse[tid] = sf[tid];

    // ---- last-block scan ----
    __threadfence();
    if (tid == 0) s_last = (atomicAdd(&g_done, 1) == NSEG - 1);
    __syncthreads();
    if (!s_last) return;

    __shared__ int tot[8];
    int wrp = tid >> 5;
    if (wrp < 7) {
        int c = wrp;
        int carry = 0;
        for (int g = 0; g < 32; g++) {
            int s = g * 32 + lane;
            int v = g_segCnt[s * 8 + c];
            int incl = v;
#pragma unroll
            for (int d = 1; d < 32; d <<= 1) {
                int n = __shfl_up_sync(0xFFFFFFFFu, incl, d);
                if (lane >= d) incl += n;
            }
            g_segOff[s * 8 + c] = carry + incl - v;
            carry += __shfl_sync(0xFFFFFFFFu, incl, 31);
        }
        if (lane == 0) tot[c] = carry;
    }
    __syncthreads();
    if (tid == 0) {
        int start = 0;
        for (int cls = 6; cls >= 0; cls--) { g_classStart[cls] = start; start += tot[cls]; }
        g_done = 0;
    }
}

// ---------------- kC: ballot-based stable compaction ----------------
__global__ void kC() {
    __shared__ int wcc[8][8];
    int t = threadIdx.x;
    int seg = blockIdx.x;
    int i = seg * SEGSZ + t;
    int cl = g_cls[i];
    int lane = t & 31, wrp = t >> 5;
    unsigned b0 = __ballot_sync(0xFFFFFFFFu, cl == 0);
    unsigned b1 = __ballot_sync(0xFFFFFFFFu, cl == 1);
    unsigned b2 = __ballot_sync(0xFFFFFFFFu, cl == 2);
    unsigned b3 = __ballot_sync(0xFFFFFFFFu, cl == 3);
    unsigned b4 = __ballot_sync(0xFFFFFFFFu, cl == 4);
    unsigned b5 = __ballot_sync(0xFFFFFFFFu, cl == 5);
    unsigned b6 = __ballot_sync(0xFFFFFFFFu, cl == 6);
    unsigned myb = (cl == 0) ? b0 : (cl == 1) ? b1 : (cl == 2) ? b2 : (cl == 3) ? b3
                 : (cl == 4) ? b4 : (cl == 5) ? b5 : b6;
    if (lane < 7) {
        unsigned bb = (lane == 0) ? b0 : (lane == 1) ? b1 : (lane == 2) ? b2 : (lane == 3) ? b3
                    : (lane == 4) ? b4 : (lane == 5) ? b5 : b6;
        wcc[wrp][lane] = __popc(bb);
    }
    __syncthreads();
    int rank = __popc(myb & ((1u << lane) - 1u));
    for (int w = 0; w < wrp; w++) rank += wcc[w][cl];
    int pos = g_classStart[cl] + g_segOff[seg * 8 + cl] + rank;
    if (pos < NSEL) g_idx[pos] = i;
}

// ---------------- kCol: warp-per-splat color sample + MLP ----------------
__global__ void __launch_bounds__(256) kCol(
        const float* __restrict__ mask, const float* __restrict__ img,
        const float* __restrict__ grid,
        const float* __restrict__ w1, const float* __restrict__ b1,
        const float* __restrict__ w2, const float* __restrict__ b2) {
    __shared__ __align__(16) float sw1t[128 * 4];   // [j][i] transposed w1 rows 0..3
    __shared__ float sb1[128];
    __shared__ __align__(16) float sw2p[128 * 20];  // [j][0..13] stride 20
    __shared__ float sb2[16];
    __shared__ float sf[101];
    int t = threadIdx.x;
    for (int k = t; k < 512; k += 256) {
        int j = k >> 2, i = k & 3;
        sw1t[k] = w1[i * 128 + j];
    }
    if (t < 128) sb1[t] = b1[t];
    for (int k = t; k < 1792; k += 256) {
        int j = k / 14, c = k - j * 14;
        sw2p[j * 20 + c] = w2[k];
    }
    if (t < 14) sb2[t] = b2[t];
    if (t >= 128 && t < 229) sf[t - 128] = g_fuse[t - 128];
    __syncthreads();

    int wid = t >> 5;
    int lane = t & 31;
    int sp = blockIdx.x * 8 + wid;
    int cell = g_idx[sp];
    int cls = g_cls[cell];
    float frac = (float)cls / 6.0f;
    float f0 = 10.0f * frac - 5.0f;
    float gx = grid[cell * 3 + 0], gy = grid[cell * 3 + 1], gz = grid[cell * 3 + 2];

    // lanes 0..5 each sample one view
    int cntv = 0;
    float cr = 0.f, cg = 0.f, cb = 0.f;
    if (lane < 6) {
        int v = lane;
        const float* F = sf + v * 16;
        float cx_ = F[0] * gx + F[1] * gy + F[2] * gz + F[9];
        float cy_ = F[3] * gx + F[4] * gy + F[5] * gz + F[10];
        float cz_ = F[6] * gx + F[7] * gy + F[8] * gz + F[11];
        float p0 = F[12] * cx_ + F[14] * cz_;
        float p1 = F[13] * cy_ + F[15] * cz_;
        float rz_ = 1.0f / cz_;
        float u = p0 * rz_;
        float w = p1 * rz_;
        if (u >= 0.f && u < 256.f && w >= 0.f && w < 256.f && cz_ > 0.01f) {
            int ui = (int)rintf(u); ui = min(max(ui, 0), 255);
            int vi = (int)rintf(w); vi = min(max(vi, 0), 255);
            int off = (v * 256 + vi) * 256 + ui;
            if (__ldg(&mask[off]) > 0.5f) {
                cntv = 1;
                const float* ip = img + (size_t)off * 3;
                cr = __ldg(ip); cg = __ldg(ip + 1); cb = __ldg(ip + 2);
            }
        }
    }
#pragma unroll
    for (int d = 16; d > 0; d >>= 1) {
        cntv += __shfl_xor_sync(0xFFFFFFFFu, cntv, d);
        cr += __shfl_xor_sync(0xFFFFFFFFu, cr, d);
        cg += __shfl_xor_sync(0xFFFFFFFFu, cg, d);
        cb += __shfl_xor_sync(0xFFFFFFFFu, cb, d);
    }
    float f1, f2, f3;
    if (cntv == 6) { f1 = cr / 6.0f; f2 = cg / 6.0f; f3 = cb / 6.0f; }
    else { f1 = f2 = f3 = FILLC; }

    // MLP: lane handles hidden units j = lane + 32*i, i=0..3
    float o14[14];
#pragma unroll
    for (int k = 0; k < 14; k++) o14[k] = 0.0f;
#pragma unroll
    for (int i = 0; i < 4; i++) {
        int j = lane + (i << 5);
        float4 wv = *(const float4*)&sw1t[j * 4];
        float acc = sb1[j] + f0 * wv.x + f1 * wv.y + f2 * wv.z + f3 * wv.w;
        float h = fmaxf(acc, 0.0f);
        const float* wr = &sw2p[j * 20];
        float4 a = *(const float4*)(wr);
        float4 b = *(const float4*)(wr + 4);
        float4 c = *(const float4*)(wr + 8);
        float2 d = *(const float2*)(wr + 12);
        o14[0] += h * a.x; o14[1] += h * a.y; o14[2] += h * a.z; o14[3] += h * a.w;
        o14[4] += h * b.x; o14[5] += h * b.y; o14[6] += h * b.z; o14[7] += h * b.w;
        o14[8] += h * c.x; o14[9] += h * c.y; o14[10] += h * c.z; o14[11] += h * c.w;
        o14[12] += h * d.x; o14[13] += h * d.y;
    }
#pragma unroll
    for (int d = 16; d > 0; d >>= 1) {
#pragma unroll
        for (int k = 0; k < 14; k++)
            o14[k] += __shfl_xor_sync(0xFFFFFFFFu, o14[k], d);
    }
#pragma unroll
    for (int k = 0; k < 14; k++) o14[k] += sb2[k];

    if (lane < 4) {
        int kb = lane * 4;
        float4 wv4;
        wv4.x = (kb + 0 < 14) ? o14[kb + 0] : 0.0f;
        wv4.y = (kb + 1 < 14) ? o14[kb + 1] : 0.0f;
        wv4.z = (kb + 2 < 14) ? o14[kb + 2] : 0.0f;
        wv4.w = (kb + 3 < 14) ? o14[kb + 3] : 0.0f;
        *(float4*)&g_o14[sp * 16 + kb] = wv4;
    }
}

// ---------------- kGeo: activations + Jacobi + splat preprocess ----------------
__global__ void __launch_bounds__(32) kGeo(
        const float* __restrict__ grid, const float* __restrict__ Ks,
        const float* __restrict__ vms, const float* __restrict__ scale_param,
        const int* __restrict__ viewnum) {
    int sp = blockIdx.x * 32 + threadIdx.x;
    int cell = g_idx[sp];
    int cls = g_cls[cell];
    float frac = (float)cls / 6.0f;
    float f0 = 10.0f * frac - 5.0f;

    float o14[14];
    {
        float4 a = *(const float4*)&g_o14[sp * 16 + 0];
        float4 b = *(const float4*)&g_o14[sp * 16 + 4];
        float4 c = *(const float4*)&g_o14[sp * 16 + 8];
        float4 d = *(const float4*)&g_o14[sp * 16 + 12];
        o14[0] = a.x; o14[1] = a.y; o14[2] = a.z; o14[3] = a.w;
        o14[4] = b.x; o14[5] = b.y; o14[6] = b.z; o14[7] = b.w;
        o14[8] = c.x; o14[9] = c.y; o14[10] = c.z; o14[11] = c.w;
        o14[12] = d.x; o14[13] = d.y;
    }

    float q0 = o14[0], q1 = o14[1], q2 = o14[2], q3 = o14[3];
    float sp0 = scale_param[0];
    float sc0 = expf(o14[4] + sp0);
    float sc1 = expf(o14[5] + sp0);
    float sc2 = expf(o14[6] + sp0);
    float col0 = fminf(fmaxf(sigmoidf(o14[8]), 0.0f), 0.99f);
    float col1 = fminf(fmaxf(sigmoidf(o14[9]), 0.0f), 0.99f);
    float col2 = fminf(fmaxf(sigmoidf(o14[10]), 0.0f), 0.99f);
    float dm0 = tanhf(o14[11]), dm1 = tanhf(o14[12]), dm2 = tanhf(o14[13]);

    float prob = sigmoidf(f0 - 0.25f);
    float tt = fminf(fmaxf((prob - 0.25f) / 0.75f, 0.0f), 1.0f);
    float opac = sigmoidf(tt);

    float cza = g_fuse[96], sza = g_fuse[97];
    float p3x = g_fuse[98], p3y = g_fuse[99], p3z = g_fuse[100];
    float gx = grid[cell * 3 + 0], gy = grid[cell * 3 + 1], gz = grid[cell * 3 + 2];
    float mlx = gx + VOX2 * dm0;
    float mly = gy + VOX2 * dm1;
    float mlz = gz + VOX2 * dm2;
    float mx = cza * mlx - sza * mly + p3x;
    float my = sza * mlx + cza * mly + p3y;
    float mz = mlz + p3z;

    float M00, M01, M02, M10, M11, M12, M20, M21, M22;
    float nf = q0 * q0 + q1 * q1 + q2 * q2 + q3 * q3;
    if (nf < 4.76837158203125e-07f) {
        M00 = 1.f; M01 = 0.f; M02 = 0.f;
        M10 = 0.f; M11 = 1.f; M12 = 0.f;
        M20 = 0.f; M21 = 0.f; M22 = 1.f;
    } else {
        float scl = sqrtf(2.0f / nf);
        float w = q0 * scl, x = q1 * scl, y = q2 * scl, z = q3 * scl;
        M00 = 1.f - y * y - z * z;
        M01 = x * y - z * w;
        M02 = x * z + y * w;
        M10 = x * y - z * w;
        M11 = 1.f;
        M12 = y * z - x * w;
        M20 = x * z - y * w;
        M21 = y * z + x * w;
        M22 = 1.f - x * x - y * y;
    }
    float r00 = cza * M00 - sza * M10, r01 = cza * M01 - sza * M11, r02 = cza * M02 - sza * M12;
    float r10 = sza * M00 + cza * M10, r11 = sza * M01 + cza * M11, r12 = sza * M02 + cza * M12;
    float r20 = M20, r21 = M21, r22 = M22;

    float A[4][4];
    const float third = 1.0f / 3.0f;
    A[0][0] = (r00 - r11 - r22) * third;
    A[0][1] = (r01 + r10) * third;
    A[0][2] = (r02 + r20) * third;
    A[0][3] = (r21 - r12) * third;
    A[1][1] = (r11 - r00 - r22) * third;
    A[1][2] = (r12 + r21) * third;
    A[1][3] = (r02 - r20) * third;
    A[2][2] = (r22 - r00 - r11) * third;
    A[2][3] = (r10 - r01) * third;
    A[3][3] = (r00 + r11 + r22) * third;
    A[1][0] = A[0][1]; A[2][0] = A[0][2]; A[3][0] = A[0][3];
    A[2][1] = A[1][2]; A[3][1] = A[1][3]; A[3][2] = A[2][3];

    float V[4][4] = {{1, 0, 0, 0}, {0, 1, 0, 0}, {0, 0, 1, 0}, {0, 0, 0, 1}};

#define JROT(p, q)                                                              \
    {                                                                           \
        float apq = A[p][q];                                                    \
        if (fabsf(apq) > 1e-12f) {                                              \
            float theta = __fdividef(A[q][q] - A[p][p], 2.0f * apq);            \
            float tJ = __fdividef(copysignf(1.0f, theta),                       \
                                  fabsf(theta) + sqrtf(theta * theta + 1.0f));  \
            float cJ = rsqrtf(tJ * tJ + 1.0f);                                  \
            float sJ = tJ * cJ;                                                 \
            _Pragma("unroll") for (int k = 0; k < 4; k++) {                     \
                float akp = A[k][p], akq = A[k][q];                             \
                A[k][p] = cJ * akp - sJ * akq;                                  \
                A[k][q] = sJ * akp + cJ * akq;                                  \
            }                                                                   \
            _Pragma("unroll") for (int k = 0; k < 4; k++) {                     \
                float apk = A[p][k], aqk = A[q][k];                             \
                A[p][k] = cJ * apk - sJ * aqk;                                  \
                A[q][k] = sJ * apk + cJ * aqk;                                  \
            }                                                                   \
            _Pragma("unroll") for (int k = 0; k < 4; k++) {                     \
                float vkp = V[k][p], vkq = V[k][q];                             \
                V[k][p] = cJ * vkp - sJ * vkq;                                  \
                V[k][q] = sJ * vkp + cJ * vkq;                                  \
            }                                                                   \
        }                                                                       \
    }

    for (int sweep = 0; sweep < 8; sweep++) {
        float off = fabsf(A[0][1]) + fabsf(A[0][2]) + fabsf(A[0][3]) +
                    fabsf(A[1][2]) + fabsf(A[1][3]) + fabsf(A[2][3]);
        if (off < 1e-9f) break;
        JROT(0, 1) JROT(0, 2) JROT(0, 3) JROT(1, 2) JROT(1, 3) JROT(2, 3)
    }
#undef JROT

    float bd = A[0][0];
    float qx = V[0][0], qy = V[1][0], qz = V[2][0], qw = V[3][0];
#pragma unroll
    for (int k = 1; k < 4; k++) {
        bool b = A[k][k] > bd;
        bd = b ? A[k][k] : bd;
        qx = b ? V[0][k] : qx;
        qy = b ? V[1][k] : qy;
        qz = b ? V[2][k] : qz;
        qw = b ? V[3][k] : qw;
    }

    float qlen = sqrtf(qw * qw + qx * qx + qy * qy + qz * qz) + 1e-12f;
    float w_ = qw / qlen, x_ = qx / qlen, y_ = qy / qlen, z_ = qz / qlen;
    float Rq[3][3] = {
        {1.f - 2.f * (y_ * y_ + z_ * z_), 2.f * (x_ * y_ - w_ * z_), 2.f * (x_ * z_ + w_ * y_)},
        {2.f * (x_ * y_ + w_ * z_), 1.f - 2.f * (x_ * x_ + z_ * z_), 2.f * (y_ * z_ - w_ * x_)},
        {2.f * (x_ * z_ - w_ * y_), 2.f * (y_ * z_ + w_ * x_), 1.f - 2.f * (x_ * x_ + y_ * y_)}};
    float s2[3] = {sc0 * sc0, sc1 * sc1, sc2 * sc2};
    float cov3[3][3];
#pragma unroll
    for (int a = 0; a < 3; a++)
#pragma unroll
        for (int bb = 0; bb < 3; bb++)
            cov3[a][bb] = Rq[a][0] * s2[0] * Rq[bb][0] + Rq[a][1] * s2[1] * Rq[bb][1]
                        + Rq[a][2] * s2[2] * Rq[bb][2];

    int view = viewnum[0];
    const float* vm2 = vms + view * 16;
    float R3[3][3] = {{vm2[0], vm2[1], vm2[2]}, {vm2[4], vm2[5], vm2[6]}, {vm2[8], vm2[9], vm2[10]}};
    float camx = R3[0][0] * mx + R3[0][1] * my + R3[0][2] * mz + vm2[3];
    float camy = R3[1][0] * mx + R3[1][1] * my + R3[1][2] * mz + vm2[7];
    float camz = R3[2][0] * mx + R3[2][1] * my + R3[2][2] * mz + vm2[11];

    float tmp[3][3], covc[3][3];
#pragma unroll
    for (int a = 0; a < 3; a++)
#pragma unroll
        for (int bb = 0; bb < 3; bb++)
            tmp[a][bb] = R3[a][0] * cov3[0][bb] + R3[a][1] * cov3[1][bb] + R3[a][2] * cov3[2][bb];
#pragma unroll
    for (int a = 0; a < 3; a++)
#pragma unroll
        for (int bb = 0; bb < 3; bb++)
            covc[a][bb] = tmp[a][0] * R3[bb][0] + tmp[a][1] * R3[bb][1] + tmp[a][2] * R3[bb][2];

    const float* K2 = Ks + view * 9;
    float fx = K2[0], fy = K2[4], cxk = K2[2], cyk = K2[5];
    float rz = 1.0f / camz;
    float J00 = fx * rz, J02 = -fx * camx * rz * rz;
    float J11 = fy * rz, J12 = -fy * camy * rz * rz;
    float t0x = J00 * covc[0][0] + J02 * covc[2][0];
    float t0y = J00 * covc[0][1] + J02 * covc[2][1];
    float t0z = J00 * covc[0][2] + J02 * covc[2][2];
    float t1y = J11 * covc[1][1] + J12 * covc[2][1];
    float t1z = J11 * covc[1][2] + J12 * covc[2][2];
    float c00 = t0x * J00 + t0z * J02;
    float c01 = t0y * J11 + t0z * J12;
    float c11 = t1y * J11 + t1z * J12;

    float a2 = c00 + 0.3f;
    float b2v = c01;
    float c2 = c11 + 0.3f;
    float det = a2 * c2 - b2v * b2v;
    float det_s = (det > 1e-12f) ? det : 1.0f;
    float cca = c2 / det_s, ccb = -b2v / det_s, ccc = a2 / det_s;
    float lam = 0.5f * (a2 + c2) + sqrtf(fmaxf(0.25f * (a2 - c2) * (a2 - c2) + b2v * b2v, 1e-12f));
    float radius = ceilf(3.0f * sqrtf(lam));
    bool valid = (camz > 0.01f) && (det > 1e-12f) && (radius > 2.0f);
    float op = valid ? opac : 0.0f;
    float mux = fx * camx * rz + cxk;
    float muy = fy * camy * rz + cyk;

    unsigned int zu = __float_as_uint(camz);
    zu = (zu & 0x80000000u) ? ~zu : (zu | 0x80000000u);
    g_keys[sp] = ((unsigned long long)zu << 32) | (unsigned)sp;

    float smax = -1e30f;
    float bx0 = 1e30f, bx1 = -1e30f, by0 = 1e30f, by1 = -1e30f;
    if (op * 255.0f >= 1.0f) {
        smax = logf(255.0f * op) + 1e-4f;
        float detM = cca * ccc - ccb * ccb;
        if (detM > 0.0f && smax > 0.0f) {
            float dxm = sqrtf(2.0f * smax * ccc / detM) + 0.02f;
            float dym = sqrtf(2.0f * smax * cca / detM) + 0.02f;
            bx0 = mux - dxm; bx1 = mux + dxm;
            by0 = muy - dym; by1 = muy + dym;
        } else if (smax > 0.0f) {
            bx0 = -1e30f; bx1 = 1e30f; by0 = -1e30f; by1 = 1e30f;
        }
    }
    g_posA[sp] = make_float4(mux, muy, cca, ccb);
    g_parA[sp] = make_float4(ccc, op, smax, 0.0f);
    g_colA[sp] = make_float4(col0, col1, col2, 0.0f);
    g_boxA[sp] = make_float4(bx0, bx1, by0, by1);
}

// ---------------- kF: stable bitonic sort by z (keys only -> permutation) ----------------
__global__ void kF() {
    __shared__ unsigned long long sk[NSEL];
    int t = threadIdx.x;
    sk[t] = g_keys[t];
    sk[t + 1024] = g_keys[t + 1024];
    __syncthreads();
    for (int k = 2; k <= NSEL; k <<= 1) {
        for (int j = k >> 1; j > 0; j >>= 1) {
            int idx = ((t & ~(j - 1)) << 1) | (t & (j - 1));
            int par = idx | j;
            bool up = ((idx & k) == 0);
            unsigned long long a = sk[idx], b = sk[par];
            if ((a > b) == up) { sk[idx] = b; sk[par] = a; }
            if (j >= 64) __syncthreads();
            else __syncwarp();
        }
        __syncthreads();
    }
    g_perm[t] = (int)(sk[t] & 0xFFFFFFFFull);
    g_perm[t + 1024] = (int)(sk[t + 1024] & 0xFFFFFFFFull);
}

// ---------------- kG1: per-(tile,segment) compositing via permutation ----------------
__global__ void kG1() {
    int tx = threadIdx.x, ty = threadIdx.y;
    int tid = ty * 16 + tx;
    int px = blockIdx.x * 16 + tx;
    int py = blockIdx.y * 16 + ty;
    int seg = blockIdx.z;
    float xs = px + 0.5f;
    float ysv = py + 0.5f;
    float tx0 = blockIdx.x * 16 + 0.5f - 1e-3f;
    float tx1 = blockIdx.x * 16 + 15.5f + 1e-3f;
    float ty0 = blockIdx.y * 16 + 0.5f - 1e-3f;
    float ty1 = blockIdx.y * 16 + 15.5f + 1e-3f;

    __shared__ float4 shP[256], shQ[256], shC[256];
    __shared__ int wcnt[8];

    int s = g_perm[seg * 256 + tid];
    float4 box = g_boxA[s];
    bool keep = (box.x <= tx1) && (box.y >= tx0) && (box.z <= ty1) && (box.w >= ty0);
    unsigned m = __ballot_sync(0xFFFFFFFFu, keep);
    int lane = tid & 31, wrp = tid >> 5;
    if (lane == 0) wcnt[wrp] = __popc(m);
    __syncthreads();
    int wbase = 0, cnt = 0;
#pragma unroll
    for (int i = 0; i < 8; i++) {
        if (i < wrp) wbase += wcnt[i];
        cnt += wcnt[i];
    }
    if (keep) {
        int p = wbase + __popc(m & ((1u << lane) - 1u));
        shP[p] = g_posA[s];
        shQ[p] = g_parA[s];
        shC[p] = g_colA[s];
    }
    __syncthreads();

    float T = 1.0f, rr = 0.f, gg = 0.f, bb = 0.f;
    for (int n = 0; n < cnt; n++) {
        float4 P = shP[n];
        float4 Q = shQ[n];
        float dx = xs - P.x, dy = ysv - P.y;
        float sigma = 0.5f * (P.z * dx * dx + Q.x * dy * dy) + P.w * dx * dy;
        if (sigma <= Q.z && sigma >= 0.0f) {
            float alpha = Q.y * __expf(-sigma);
            if (alpha >= (1.0f / 255.0f)) {
                alpha = fminf(alpha, 0.999f);
                float wgt = alpha * T;
                float4 C = shC[n];
                rr += wgt * C.x; gg += wgt * C.y; bb += wgt * C.z;
                T *= (1.0f - alpha);
                if (T < 1e-7f) break;
            }
        }
    }
    g_seg[seg * 65536 + py * 256 + px] = make_float4(rr, gg, bb, T);
}

// ---------------- kG2: combine segments + background ----------------
__global__ void kG2(const float* __restrict__ bg, float* __restrict__ out) {
    int pix = blockIdx.x * 256 + threadIdx.x;
    float T = 1.0f, rr = 0.f, gg = 0.f, bb = 0.f;
#pragma unroll
    for (int z = 0; z < 8; z++) {
        float4 sgm = g_seg[z * 65536 + pix];
        rr += T * sgm.x; gg += T * sgm.y; bb += T * sgm.z;
        T *= sgm.w;
    }
    float bgr = bg[0], bgg = bg[1], bgb = bg[2];
    out[pix * 3 + 0] = fminf(fmaxf(rr + T * bgr, 0.0f), 1.0f);
    out[pix * 3 + 1] = fminf(fmaxf(gg + T * bgg, 0.0f), 1.0f);
    out[pix * 3 + 2] = fminf(fmaxf(bb + T * bgb, 0.0f), 1.0f);
    out[196608 + pix] = 1.0f - T;
}

// ---------------- launch ----------------
extern "C" void kernel_launch(void* const* d_in, const int* in_sizes, int n_in,
                              void* d_out, int out_size) {
    const float* mask = (const float*)d_in[0];
    const float* img = (const float*)d_in[1];
    const float* p3d = (const float*)d_in[2];
    const float* angle = (const float*)d_in[3];
    const float* grid = (const float*)d_in[4];
    const float* Ks = (const float*)d_in[5];
    const float* vms = (const float*)d_in[6];
    const float* w1 = (const float*)d_in[7];
    const float* b1 = (const float*)d_in[8];
    const float* w2 = (const float*)d_in[9];
    const float* b2 = (const float*)d_in[10];
    const float* scale_param = (const float*)d_in[11];
    const float* bg = (const float*)d_in[12];
    const int* viewnum = (const int*)d_in[13];
    float* out = (float*)d_out;

    kA<<<NSEG, SEGSZ>>>(mask, grid, p3d, angle, Ks, vms);
    kC<<<NSEG, SEGSZ>>>();
    kCol<<<NSEL / 8, 256>>>(mask, img, grid, w1, b1, w2, b2);
    kGeo<<<NSEL / 32, 32>>>(grid, Ks, vms, scale_param, viewnum);
    kF<<<1, 1024>>>();
    dim3 gb1(16, 16, 8), tb1(16, 16);
    kG1<<<gb1, tb1>>>();
    kG2<<<256, 256>>>(bg, out);
}

// round 12
// speedup vs baseline: 1.7589x; 1.0769x over previous
#include <cuda_runtime.h>
#include <cstdint>

#define NCELL 262144
#define NSEG  1024
#define SEGSZ 256
#define NSEL  2048
#define NZSEG 16
#define NMASK 393216
#define VOX2  0.005625f   /* 2 * (0.18/64) */
#define FILLC 0.45f

// ---------------- device scratch (static, no allocs) ----------------
__device__ unsigned char g_cls[NCELL];
__device__ unsigned g_maskbits[NMASK / 32];
__device__ int g_segCnt[NSEG * 8];
__device__ int g_segOff[NSEG * 8];
__device__ int g_classStart[8];
__device__ int g_idx[NSEL];
__device__ int g_done;
__device__ float g_fuse[128];
__device__ float g_o14[NSEL * 16];
__device__ unsigned long long g_keys[NSEL];
__device__ int g_perm[NSEL];
__device__ float4 g_posA[NSEL], g_parA[NSEL], g_colA[NSEL], g_boxA[NSEL];
__device__ float4 g_seg[NZSEG * 65536];

__device__ __forceinline__ float sigmoidf(float x) { return 1.0f / (1.0f + expf(-x)); }

// ---------------- kMask: pack mask>0.5 into bitfield (ALL 393216 elements) ----------------
__global__ void kMask(const float* __restrict__ mask) {
    int i = blockIdx.x * 256 + threadIdx.x;
    bool b = mask[i] > 0.5f;
    unsigned m = __ballot_sync(0xFFFFFFFFu, b);
    if ((threadIdx.x & 31) == 0) g_maskbits[i >> 5] = m;
}

// ---------------- kA: fuse-coeff init + projection + bit-probe count + histogram + scan tail ----------------
__global__ void kA(const float* __restrict__ grid,
                   const float* __restrict__ p3d, const float* __restrict__ angle,
                   const float* __restrict__ Ks, const float* __restrict__ vms) {
    __shared__ int hist[8];
    __shared__ float sf[101];
    __shared__ int s_last;
    int tid = threadIdx.x;
    if (tid < 8) hist[tid] = 0;
    if (tid < 6) {
        int v = tid;
        float ang = angle[0];
        float ca = cosf(ang), sa = sinf(ang);
        const float* vm = vms + v * 16;
        float* F = sf + v * 16;
        for (int r = 0; r < 3; r++) {
            float R0 = vm[r * 4 + 0], R1 = vm[r * 4 + 1], R2 = vm[r * 4 + 2];
            F[r * 3 + 0] = R0 * ca + R1 * sa;
            F[r * 3 + 1] = -R0 * sa + R1 * ca;
            F[r * 3 + 2] = R2;
            F[9 + r] = R0 * p3d[0] + R1 * p3d[1] + R2 * p3d[2] + vm[r * 4 + 3];
        }
        const float* K = Ks + v * 9;
        F[12] = K[0]; F[13] = K[4]; F[14] = K[2]; F[15] = K[5];
    } else if (tid == 6) {
        float ang = angle[0];
        sf[96] = cosf(ang); sf[97] = sinf(ang);
        sf[98] = p3d[0]; sf[99] = p3d[1]; sf[100] = p3d[2];
    }
    __syncthreads();

    int i = blockIdx.x * SEGSZ + tid;
    float gx = grid[i * 3 + 0], gy = grid[i * 3 + 1], gz = grid[i * 3 + 2];

    int cnt = 0;
#pragma unroll
    for (int v = 0; v < 6; v++) {
        const float* F = sf + v * 16;
        float cx_ = F[0] * gx + F[1] * gy + F[2] * gz + F[9];
        float cy_ = F[3] * gx + F[4] * gy + F[5] * gz + F[10];
        float cz_ = F[6] * gx + F[7] * gy + F[8] * gz + F[11];
        float p0 = F[12] * cx_ + F[14] * cz_;
        float p1 = F[13] * cy_ + F[15] * cz_;
        float rz_ = 1.0f / cz_;
        float u = p0 * rz_;
        float w = p1 * rz_;
        if (u >= 0.f && u < 256.f && w >= 0.f && w < 256.f && cz_ > 0.01f) {
            int ui = (int)rintf(u); ui = min(max(ui, 0), 255);
            int vi = (int)rintf(w); vi = min(max(vi, 0), 255);
            int off = (v * 256 + vi) * 256 + ui;
            cnt += (g_maskbits[off >> 5] >> (off & 31)) & 1;
        }
    }
    g_cls[i] = (unsigned char)cnt;

    int lane = tid & 31;
#pragma unroll
    for (int c = 0; c < 7; c++) {
        unsigned m = __ballot_sync(0xFFFFFFFFu, cnt == c);
        if (lane == 0 && m) atomicAdd(&hist[c], __popc(m));
    }
    __syncthreads();
    if (tid < 8) g_segCnt[blockIdx.x * 8 + tid] = hist[tid];
    if (blockIdx.x == 0 && tid < 101) g_fuse[tid] = sf[tid];

    // ---- last-block scan ----
    __threadfence();
    if (tid == 0) s_last = (atomicAdd(&g_done, 1) == NSEG - 1);
    __syncthreads();
    if (!s_last) return;

    __shared__ int tot[8];
    int wrp = tid >> 5;
    if (wrp < 7) {
        int c = wrp;
        int carry = 0;
        for (int g = 0; g < 32; g++) {
            int s = g * 32 + lane;
            int v = g_segCnt[s * 8 + c];
            int incl = v;
#pragma unroll
            for (int d = 1; d < 32; d <<= 1) {
                int n = __shfl_up_sync(0xFFFFFFFFu, incl, d);
                if (lane >= d) incl += n;
            }
            g_segOff[s * 8 + c] = carry + incl - v;
            carry += __shfl_sync(0xFFFFFFFFu, incl, 31);
        }
        if (lane == 0) tot[c] = carry;
    }
    __syncthreads();
    if (tid == 0) {
        int start = 0;
        for (int cls = 6; cls >= 0; cls--) { g_classStart[cls] = start; start += tot[cls]; }
        g_done = 0;
    }
}

// ---------------- kC: ballot-based stable compaction ----------------
__global__ void kC() {
    __shared__ int wcc[8][8];
    int t = threadIdx.x;
    int seg = blockIdx.x;
    int i = seg * SEGSZ + t;
    int cl = g_cls[i];
    int lane = t & 31, wrp = t >> 5;
    unsigned b0 = __ballot_sync(0xFFFFFFFFu, cl == 0);
    unsigned b1 = __ballot_sync(0xFFFFFFFFu, cl == 1);
    unsigned b2 = __ballot_sync(0xFFFFFFFFu, cl == 2);
    unsigned b3 = __ballot_sync(0xFFFFFFFFu, cl == 3);
    unsigned b4 = __ballot_sync(0xFFFFFFFFu, cl == 4);
    unsigned b5 = __ballot_sync(0xFFFFFFFFu, cl == 5);
    unsigned b6 = __ballot_sync(0xFFFFFFFFu, cl == 6);
    unsigned myb = (cl == 0) ? b0 : (cl == 1) ? b1 : (cl == 2) ? b2 : (cl == 3) ? b3
                 : (cl == 4) ? b4 : (cl == 5) ? b5 : b6;
    if (lane < 7) {
        unsigned bb = (lane == 0) ? b0 : (lane == 1) ? b1 : (lane == 2) ? b2 : (lane == 3) ? b3
                    : (lane == 4) ? b4 : (lane == 5) ? b5 : b6;
        wcc[wrp][lane] = __popc(bb);
    }
    __syncthreads();
    int rank = __popc(myb & ((1u << lane) - 1u));
    for (int w = 0; w < wrp; w++) rank += wcc[w][cl];
    int pos = g_classStart[cl] + g_segOff[seg * 8 + cl] + rank;
    if (pos < NSEL) g_idx[pos] = i;
}

// ---------------- kCol: warp-per-splat color sample + MLP ----------------
__global__ void __launch_bounds__(256) kCol(
        const float* __restrict__ img, const float* __restrict__ grid,
        const float* __restrict__ w1, const float* __restrict__ b1,
        const float* __restrict__ w2, const float* __restrict__ b2) {
    __shared__ __align__(16) float sw1t[128 * 4];
    __shared__ float sb1[128];
    __shared__ __align__(16) float sw2p[128 * 20];
    __shared__ float sb2[16];
    __shared__ float sf[101];
    int t = threadIdx.x;
    for (int k = t; k < 512; k += 256) {
        int j = k >> 2, i = k & 3;
        sw1t[k] = w1[i * 128 + j];
    }
    if (t < 128) sb1[t] = b1[t];
    for (int k = t; k < 1792; k += 256) {
        int j = k / 14, c = k - j * 14;
        sw2p[j * 20 + c] = w2[k];
    }
    if (t < 14) sb2[t] = b2[t];
    if (t >= 128 && t < 229) sf[t - 128] = g_fuse[t - 128];
    __syncthreads();

    int wid = t >> 5;
    int lane = t & 31;
    int sp = blockIdx.x * 8 + wid;
    int cell = g_idx[sp];
    int cls = g_cls[cell];
    float frac = (float)cls / 6.0f;
    float f0 = 10.0f * frac - 5.0f;
    float gx = grid[cell * 3 + 0], gy = grid[cell * 3 + 1], gz = grid[cell * 3 + 2];

    int cntv = 0;
    float cr = 0.f, cg = 0.f, cb = 0.f;
    if (lane < 6) {
        int v = lane;
        const float* F = sf + v * 16;
        float cx_ = F[0] * gx + F[1] * gy + F[2] * gz + F[9];
        float cy_ = F[3] * gx + F[4] * gy + F[5] * gz + F[10];
        float cz_ = F[6] * gx + F[7] * gy + F[8] * gz + F[11];
        float p0 = F[12] * cx_ + F[14] * cz_;
        float p1 = F[13] * cy_ + F[15] * cz_;
        float rz_ = 1.0f / cz_;
        float u = p0 * rz_;
        float w = p1 * rz_;
        if (u >= 0.f && u < 256.f && w >= 0.f && w < 256.f && cz_ > 0.01f) {
            int ui = (int)rintf(u); ui = min(max(ui, 0), 255);
            int vi = (int)rintf(w); vi = min(max(vi, 0), 255);
            int off = (v * 256 + vi) * 256 + ui;
            if ((g_maskbits[off >> 5] >> (off & 31)) & 1) {
                cntv = 1;
                const float* ip = img + (size_t)off * 3;
                cr = __ldg(ip); cg = __ldg(ip + 1); cb = __ldg(ip + 2);
            }
        }
    }
#pragma unroll
    for (int d = 16; d > 0; d >>= 1) {
        cntv += __shfl_xor_sync(0xFFFFFFFFu, cntv, d);
        cr += __shfl_xor_sync(0xFFFFFFFFu, cr, d);
        cg += __shfl_xor_sync(0xFFFFFFFFu, cg, d);
        cb += __shfl_xor_sync(0xFFFFFFFFu, cb, d);
    }
    float f1, f2, f3;
    if (cntv == 6) { f1 = cr / 6.0f; f2 = cg / 6.0f; f3 = cb / 6.0f; }
    else { f1 = f2 = f3 = FILLC; }

    float o14[14];
#pragma unroll
    for (int k = 0; k < 14; k++) o14[k] = 0.0f;
#pragma unroll
    for (int i = 0; i < 4; i++) {
        int j = lane + (i << 5);
        float4 wv = *(const float4*)&sw1t[j * 4];
        float acc = sb1[j] + f0 * wv.x + f1 * wv.y + f2 * wv.z + f3 * wv.w;
        float h = fmaxf(acc, 0.0f);
        const float* wr = &sw2p[j * 20];
        float4 a = *(const float4*)(wr);
        float4 b = *(const float4*)(wr + 4);
        float4 c = *(const float4*)(wr + 8);
        float2 d = *(const float2*)(wr + 12);
        o14[0] += h * a.x; o14[1] += h * a.y; o14[2] += h * a.z; o14[3] += h * a.w;
        o14[4] += h * b.x; o14[5] += h * b.y; o14[6] += h * b.z; o14[7] += h * b.w;
        o14[8] += h * c.x; o14[9] += h * c.y; o14[10] += h * c.z; o14[11] += h * c.w;
        o14[12] += h * d.x; o14[13] += h * d.y;
    }
#pragma unroll
    for (int d = 16; d > 0; d >>= 1) {
#pragma unroll
        for (int k = 0; k < 14; k++)
            o14[k] += __shfl_xor_sync(0xFFFFFFFFu, o14[k], d);
    }
#pragma unroll
    for (int k = 0; k < 14; k++) o14[k] += sb2[k];

    if (lane < 4) {
        int kb = lane * 4;
        float4 wv4;
        wv4.x = (kb + 0 < 14) ? o14[kb + 0] : 0.0f;
        wv4.y = (kb + 1 < 14) ? o14[kb + 1] : 0.0f;
        wv4.z = (kb + 2 < 14) ? o14[kb + 2] : 0.0f;
        wv4.w = (kb + 3 < 14) ? o14[kb + 3] : 0.0f;
        *(float4*)&g_o14[sp * 16 + kb] = wv4;
    }
}

// ---------------- kGeo: activations + Jacobi (paired order) + splat preprocess ----------------
__global__ void __launch_bounds__(32) kGeo(
        const float* __restrict__ grid, const float* __restrict__ Ks,
        const float* __restrict__ vms, const float* __restrict__ scale_param,
        const int* __restrict__ viewnum) {
    int sp = blockIdx.x * 32 + threadIdx.x;
    int cell = g_idx[sp];
    int cls = g_cls[cell];
    float frac = (float)cls / 6.0f;
    float f0 = 10.0f * frac - 5.0f;

    float o14[14];
    {
        float4 a = *(const float4*)&g_o14[sp * 16 + 0];
        float4 b = *(const float4*)&g_o14[sp * 16 + 4];
        float4 c = *(const float4*)&g_o14[sp * 16 + 8];
        float4 d = *(const float4*)&g_o14[sp * 16 + 12];
        o14[0] = a.x; o14[1] = a.y; o14[2] = a.z; o14[3] = a.w;
        o14[4] = b.x; o14[5] = b.y; o14[6] = b.z; o14[7] = b.w;
        o14[8] = c.x; o14[9] = c.y; o14[10] = c.z; o14[11] = c.w;
        o14[12] = d.x; o14[13] = d.y;
    }

    float q0 = o14[0], q1 = o14[1], q2 = o14[2], q3 = o14[3];
    float sp0 = scale_param[0];
    float sc0 = expf(o14[4] + sp0);
    float sc1 = expf(o14[5] + sp0);
    float sc2 = expf(o14[6] + sp0);
    float col0 = fminf(fmaxf(sigmoidf(o14[8]), 0.0f), 0.99f);
    float col1 = fminf(fmaxf(sigmoidf(o14[9]), 0.0f), 0.99f);
    float col2 = fminf(fmaxf(sigmoidf(o14[10]), 0.0f), 0.99f);
    float dm0 = tanhf(o14[11]), dm1 = tanhf(o14[12]), dm2 = tanhf(o14[13]);

    float prob = sigmoidf(f0 - 0.25f);
    float tt = fminf(fmaxf((prob - 0.25f) / 0.75f, 0.0f), 1.0f);
    float opac = sigmoidf(tt);

    float cza = g_fuse[96], sza = g_fuse[97];
    float p3x = g_fuse[98], p3y = g_fuse[99], p3z = g_fuse[100];
    float gx = grid[cell * 3 + 0], gy = grid[cell * 3 + 1], gz = grid[cell * 3 + 2];
    float mlx = gx + VOX2 * dm0;
    float mly = gy + VOX2 * dm1;
    float mlz = gz + VOX2 * dm2;
    float mx = cza * mlx - sza * mly + p3x;
    float my = sza * mlx + cza * mly + p3y;
    float mz = mlz + p3z;

    float M00, M01, M02, M10, M11, M12, M20, M21, M22;
    float nf = q0 * q0 + q1 * q1 + q2 * q2 + q3 * q3;
    if (nf < 4.76837158203125e-07f) {
        M00 = 1.f; M01 = 0.f; M02 = 0.f;
        M10 = 0.f; M11 = 1.f; M12 = 0.f;
        M20 = 0.f; M21 = 0.f; M22 = 1.f;
    } else {
        float scl = sqrtf(2.0f / nf);
        float w = q0 * scl, x = q1 * scl, y = q2 * scl, z = q3 * scl;
        M00 = 1.f - y * y - z * z;
        M01 = x * y - z * w;
        M02 = x * z + y * w;
        M10 = x * y - z * w;
        M11 = 1.f;
        M12 = y * z - x * w;
        M20 = x * z - y * w;
        M21 = y * z + x * w;
        M22 = 1.f - x * x - y * y;
    }
    float r00 = cza * M00 - sza * M10, r01 = cza * M01 - sza * M11, r02 = cza * M02 - sza * M12;
    float r10 = sza * M00 + cza * M10, r11 = sza * M01 + cza * M11, r12 = sza * M02 + cza * M12;
    float r20 = M20, r21 = M21, r22 = M22;

    float A[4][4];
    const float third = 1.0f / 3.0f;
    A[0][0] = (r00 - r11 - r22) * third;
    A[0][1] = (r01 + r10) * third;
    A[0][2] = (r02 + r20) * third;
    A[0][3] = (r21 - r12) * third;
    A[1][1] = (r11 - r00 - r22) * third;
    A[1][2] = (r12 + r21) * third;
    A[1][3] = (r02 - r20) * third;
    A[2][2] = (r22 - r00 - r11) * third;
    A[2][3] = (r10 - r01) * third;
    A[3][3] = (r00 + r11 + r22) * third;
    A[1][0] = A[0][1]; A[2][0] = A[0][2]; A[3][0] = A[0][3];
    A[2][1] = A[1][2]; A[3][1] = A[1][3]; A[3][2] = A[2][3];

    float V[4][4] = {{1, 0, 0, 0}, {0, 1, 0, 0}, {0, 0, 1, 0}, {0, 0, 0, 1}};

#define JROT(p, q)                                                              \
    {                                                                           \
        float apq = A[p][q];                                                    \
        if (fabsf(apq) > 1e-12f) {                                              \
            float theta = __fdividef(A[q][q] - A[p][p], 2.0f * apq);            \
            float tJ = __fdividef(copysignf(1.0f, theta),                       \
                                  fabsf(theta) + sqrtf(theta * theta + 1.0f));  \
            float cJ = rsqrtf(tJ * tJ + 1.0f);                                  \
            float sJ = tJ * cJ;                                                 \
            _Pragma("unroll") for (int k = 0; k < 4; k++) {                     \
                float akp = A[k][p], akq = A[k][q];                             \
                A[k][p] = cJ * akp - sJ * akq;                                  \
                A[k][q] = sJ * akp + cJ * akq;                                  \
            }                                                                   \
            _Pragma("unroll") for (int k = 0; k < 4; k++) {                     \
                float apk = A[p][k], aqk = A[q][k];                             \
                A[p][k] = cJ * apk - sJ * aqk;                                  \
                A[q][k] = sJ * apk + cJ * aqk;                                  \
            }                                                                   \
            _Pragma("unroll") for (int k = 0; k < 4; k++) {                     \
                float vkp = V[k][p], vkq = V[k][q];                             \
                V[k][p] = cJ * vkp - sJ * vkq;                                  \
                V[k][q] = sJ * vkp + cJ * vkq;                                  \
            }                                                                   \
        }                                                                       \
    }

    // commuting-pair cyclic order: the MUFU chains of each pair overlap
    for (int sweep = 0; sweep < 8; sweep++) {
        float off = fabsf(A[0][1]) + fabsf(A[0][2]) + fabsf(A[0][3]) +
                    fabsf(A[1][2]) + fabsf(A[1][3]) + fabsf(A[2][3]);
        if (off < 1e-8f) break;
        JROT(0, 1) JROT(2, 3) JROT(0, 2) JROT(1, 3) JROT(0, 3) JROT(1, 2)
    }
#undef JROT

    float bd = A[0][0];
    float qx = V[0][0], qy = V[1][0], qz = V[2][0], qw = V[3][0];
#pragma unroll
    for (int k = 1; k < 4; k++) {
        bool b = A[k][k] > bd;
        bd = b ? A[k][k] : bd;
        qx = b ? V[0][k] : qx;
        qy = b ? V[1][k] : qy;
        qz = b ? V[2][k] : qz;
        qw = b ? V[3][k] : qw;
    }

    float qlen = sqrtf(qw * qw + qx * qx + qy * qy + qz * qz) + 1e-12f;
    float w_ = qw / qlen, x_ = qx / qlen, y_ = qy / qlen, z_ = qz / qlen;
    float Rq[3][3] = {
        {1.f - 2.f * (y_ * y_ + z_ * z_), 2.f * (x_ * y_ - w_ * z_), 2.f * (x_ * z_ + w_ * y_)},
        {2.f * (x_ * y_ + w_ * z_), 1.f - 2.f * (x_ * x_ + z_ * z_), 2.f * (y_ * z_ - w_ * x_)},
        {2.f * (x_ * z_ - w_ * y_), 2.f * (y_ * z_ + w_ * x_), 1.f - 2.f * (x_ * x_ + y_ * y_)}};
    float s2[3] = {sc0 * sc0, sc1 * sc1, sc2 * sc2};
    float cov3[3][3];
#pragma unroll
    for (int a = 0; a < 3; a++)
#pragma unroll
        for (int bb = 0; bb < 3; bb++)
            cov3[a][bb] = Rq[a][0] * s2[0] * Rq[bb][0] + Rq[a][1] * s2[1] * Rq[bb][1]
                        + Rq[a][2] * s2[2] * Rq[bb][2];

    int view = viewnum[0];
    const float* vm2 = vms + view * 16;
    float R3[3][3] = {{vm2[0], vm2[1], vm2[2]}, {vm2[4], vm2[5], vm2[6]}, {vm2[8], vm2[9], vm2[10]}};
    float camx = R3[0][0] * mx + R3[0][1] * my + R3[0][2] * mz + vm2[3];
    float camy = R3[1][0] * mx + R3[1][1] * my + R3[1][2] * mz + vm2[7];
    float camz = R3[2][0] * mx + R3[2][1] * my + R3[2][2] * mz + vm2[11];

    float tmp[3][3], covc[3][3];
#pragma unroll
    for (int a = 0; a < 3; a++)
#pragma unroll
        for (int bb = 0; bb < 3; bb++)
            tmp[a][bb] = R3[a][0] * cov3[0][bb] + R3[a][1] * cov3[1][bb] + R3[a][2] * cov3[2][bb];
#pragma unroll
    for (int a = 0; a < 3; a++)
#pragma unroll
        for (int bb = 0; bb < 3; bb++)
            covc[a][bb] = tmp[a][0] * R3[bb][0] + tmp[a][1] * R3[bb][1] + tmp[a][2] * R3[bb][2];

    const float* K2 = Ks + view * 9;
    float fx = K2[0], fy = K2[4], cxk = K2[2], cyk = K2[5];
    float rz = 1.0f / camz;
    float J00 = fx * rz, J02 = -fx * camx * rz * rz;
    float J11 = fy * rz, J12 = -fy * camy * rz * rz;
    float t0x = J00 * covc[0][0] + J02 * covc[2][0];
    float t0y = J00 * covc[0][1] + J02 * covc[2][1];
    float t0z = J00 * covc[0][2] + J02 * covc[2][2];
    float t1y = J11 * covc[1][1] + J12 * covc[2][1];
    float t1z = J11 * covc[1][2] + J12 * covc[2][2];
    float c00 = t0x * J00 + t0z * J02;
    float c01 = t0y * J11 + t0z * J12;
    float c11 = t1y * J11 + t1z * J12;

    float a2 = c00 + 0.3f;
    float b2v = c01;
    float c2 = c11 + 0.3f;
    float det = a2 * c2 - b2v * b2v;
    float det_s = (det > 1e-12f) ? det : 1.0f;
    float cca = c2 / det_s, ccb = -b2v / det_s, ccc = a2 / det_s;
    float lam = 0.5f * (a2 + c2) + sqrtf(fmaxf(0.25f * (a2 - c2) * (a2 - c2) + b2v * b2v, 1e-12f));
    float radius = ceilf(3.0f * sqrtf(lam));
    bool valid = (camz > 0.01f) && (det > 1e-12f) && (radius > 2.0f);
    float op = valid ? opac : 0.0f;
    float mux = fx * camx * rz + cxk;
    float muy = fy * camy * rz + cyk;

    unsigned int zu = __float_as_uint(camz);
    zu = (zu & 0x80000000u) ? ~zu : (zu | 0x80000000u);
    g_keys[sp] = ((unsigned long long)zu << 32) | (unsigned)sp;

    float smax = -1e30f;
    float bx0 = 1e30f, bx1 = -1e30f, by0 = 1e30f, by1 = -1e30f;
    if (op * 255.0f >= 1.0f) {
        smax = logf(255.0f * op) + 1e-4f;
        float detM = cca * ccc - ccb * ccb;
        if (detM > 0.0f && smax > 0.0f) {
            float dxm = sqrtf(2.0f * smax * ccc / detM) + 0.02f;
            float dym = sqrtf(2.0f * smax * cca / detM) + 0.02f;
            bx0 = mux - dxm; bx1 = mux + dxm;
            by0 = muy - dym; by1 = muy + dym;
        } else if (smax > 0.0f) {
            bx0 = -1e30f; bx1 = 1e30f; by0 = -1e30f; by1 = 1e30f;
        }
    }
    g_posA[sp] = make_float4(mux, muy, cca, ccb);
    g_parA[sp] = make_float4(ccc, op, smax, 0.0f);
    g_colA[sp] = make_float4(col0, col1, col2, 0.0f);
    g_boxA[sp] = make_float4(bx0, bx1, by0, by1);
}

// ---------------- kF: stable bitonic sort by z (keys only -> permutation) ----------------
__global__ void kF() {
    __shared__ unsigned long long sk[NSEL];
    int t = threadIdx.x;
    sk[t] = g_keys[t];
    sk[t + 1024] = g_keys[t + 1024];
    __syncthreads();
    for (int k = 2; k <= NSEL; k <<= 1) {
        for (int j = k >> 1; j > 0; j >>= 1) {
            int idx = ((t & ~(j - 1)) << 1) | (t & (j - 1));
            int par = idx | j;
            bool up = ((idx & k) == 0);
            unsigned long long a = sk[idx], b = sk[par];
            if ((a > b) == up) { sk[idx] = b; sk[par] = a; }
            if (j >= 64) __syncthreads();
            else __syncwarp();
        }
        __syncthreads();
    }
    g_perm[t] = (int)(sk[t] & 0xFFFFFFFFull);
    g_perm[t + 1024] = (int)(sk[t + 1024] & 0xFFFFFFFFull);
}

// ---------------- kG1: per-(tile,zseg) compositing via permutation ----------------
__global__ void kG1() {
    int tx = threadIdx.x, ty = threadIdx.y;
    int tid = ty * 16 + tx;
    int px = blockIdx.x * 16 + tx;
    int py = blockIdx.y * 16 + ty;
    int seg = blockIdx.z;
    float xs = px + 0.5f;
    float ysv = py + 0.5f;
    float tx0 = blockIdx.x * 16 + 0.5f - 1e-3f;
    float tx1 = blockIdx.x * 16 + 15.5f + 1e-3f;
    float ty0 = blockIdx.y * 16 + 0.5f - 1e-3f;
    float ty1 = blockIdx.y * 16 + 15.5f + 1e-3f;

    __shared__ float4 shP[128], shQ[128], shC[128];
    __shared__ int wcnt[4];

    int lane = tid & 31, wrp = tid >> 5;
    bool keep = false;
    int s = 0;
    unsigned m = 0;
    if (tid < 128) {
        s = g_perm[seg * 128 + tid];
        float4 box = g_boxA[s];
        keep = (box.x <= tx1) && (box.y >= tx0) && (box.z <= ty1) && (box.w >= ty0);
        m = __ballot_sync(0xFFFFFFFFu, keep);
        if (lane == 0) wcnt[wrp] = __popc(m);
    }
    __syncthreads();
    int cnt = wcnt[0] + wcnt[1] + wcnt[2] + wcnt[3];
    if (keep) {
        int wbase = 0;
#pragma unroll
        for (int i = 0; i < 4; i++)
            if (i < wrp) wbase += wcnt[i];
        int p = wbase + __popc(m & ((1u << lane) - 1u));
        shP[p] = g_posA[s];
        shQ[p] = g_parA[s];
        shC[p] = g_colA[s];
    }
    __syncthreads();

    float T = 1.0f, rr = 0.f, gg = 0.f, bb = 0.f;
    for (int n = 0; n < cnt; n++) {
        float4 P = shP[n];
        float4 Q = shQ[n];
        float dx = xs - P.x, dy = ysv - P.y;
        float sigma = 0.5f * (P.z * dx * dx + Q.x * dy * dy) + P.w * dx * dy;
        if (sigma <= Q.z && sigma >= 0.0f) {
            float alpha = Q.y * __expf(-sigma);
            if (alpha >= (1.0f / 255.0f)) {
                alpha = fminf(alpha, 0.999f);
                float wgt = alpha * T;
                float4 C = shC[n];
                rr += wgt * C.x; gg += wgt * C.y; bb += wgt * C.z;
                T *= (1.0f - alpha);
                if (T < 1e-7f) break;
            }
        }
    }
    g_seg[seg * 65536 + py * 256 + px] = make_float4(rr, gg, bb, T);
}

// ---------------- kG2: combine segments + background ----------------
__global__ void kG2(const float* __restrict__ bg, float* __restrict__ out) {
    int pix = blockIdx.x * 256 + threadIdx.x;
    float T = 1.0f, rr = 0.f, gg = 0.f, bb = 0.f;
#pragma unroll
    for (int z = 0; z < NZSEG; z++) {
        float4 sgm = g_seg[z * 65536 + pix];
        rr += T * sgm.x; gg += T * sgm.y; bb += T * sgm.z;
        T *= sgm.w;
    }
    float bgr = bg[0], bgg = bg[1], bgb = bg[2];
    out[pix * 3 + 0] = fminf(fmaxf(rr + T * bgr, 0.0f), 1.0f);
    out[pix * 3 + 1] = fminf(fmaxf(gg + T * bgg, 0.0f), 1.0f);
    out[pix * 3 + 2] = fminf(fmaxf(bb + T * bgb, 0.0f), 1.0f);
    out[196608 + pix] = 1.0f - T;
}

// ---------------- launch ----------------
extern "C" void kernel_launch(void* const* d_in, const int* in_sizes, int n_in,
                              void* d_out, int out_size) {
    const float* mask = (const float*)d_in[0];
    const float* img = (const float*)d_in[1];
    const float* p3d = (const float*)d_in[2];
    const float* angle = (const float*)d_in[3];
    const float* grid = (const float*)d_in[4];
    const float* Ks = (const float*)d_in[5];
    const float* vms = (const float*)d_in[6];
    const float* w1 = (const float*)d_in[7];
    const float* b1 = (const float*)d_in[8];
    const float* w2 = (const float*)d_in[9];
    const float* b2 = (const float*)d_in[10];
    const float* scale_param = (const float*)d_in[11];
    const float* bg = (const float*)d_in[12];
    const int* viewnum = (const int*)d_in[13];
    float* out = (float*)d_out;

    kMask<<<NMASK / 256, 256>>>(mask);
    kA<<<NSEG, SEGSZ>>>(grid, p3d, angle, Ks, vms);
    kC<<<NSEG, SEGSZ>>>();
    kCol<<<NSEL / 8, 256>>>(img, grid, w1, b1, w2, b2);
    kGeo<<<NSEL / 32, 32>>>(grid, Ks, vms, scale_param, viewnum);
    kF<<<1, 1024>>>();
    dim3 gb1(16, 16, NZSEG), tb1(16, 16);
    kG1<<<gb1, tb1>>>();
    kG2<<<256, 256>>>(bg, out);
}